// round 4
// baseline (speedup 1.0000x reference)
#include <cuda_runtime.h>
#include <cstdint>

#define SEQ   20
#define BATCH 16384
#define INP   2
#define HID   256
#define EMB   64
#define TLEN  30
#define NG    1024          /* 4*HID */
#define KP    320           /* 256 h + 64 x */

#define M_CTA  128
#define N_CTA  64
#define A_TILE 16384        /* 128 rows x 128B */
#define W_TILE 8192         /* 64 rows x 128B */
#define STAGE_BYTES (A_TILE + W_TILE)       /* 24KB */
#define NCHUNK 5
#define SMEM_DYN_TOTAL (NCHUNK * STAGE_BYTES) /* 120KB */

// ---------------- device scratch ----------------
// W packed int8: [n][640] = p1[320] | p2[320]; k order: [h 0..255 | x 256..319]
__device__ int8_t g_W8_enc[NG * 640];
__device__ int8_t g_W8_dec[NG * 640];
__device__ float  g_Wf[NG * 320];       // temp fp32 (reused enc->dec)
__device__ unsigned g_maxu[4];          // |w| max bits: [enc_h, enc_x, dec_h, dec_x]
__device__ float  g_cv[4];              // epilogue consts: [enc_h, enc_x, dec_h, dec_x]
__device__ float  g_bias_enc[NG];
__device__ float  g_bias_dec[NG];
// H state: [row][512] = q1[256] | q2[256]
__device__ int8_t g_H[2][BATCH * 512];
__device__ float  g_c[BATCH * HID];
// encoder x (prescaled /8): [t*B + row][128] = q1[64] | q2[64]
__device__ int8_t g_Xe[SEQ * BATCH * 128];
__device__ int8_t g_Xd[BATCH * 128];

// ---------------- helpers ----------------
__device__ __forceinline__ uint32_t smem_to_u32(const void* p) {
    uint32_t a;
    asm("{ .reg .u64 t; cvta.to.shared.u64 t, %1; cvt.u32.u64 %0, t; }"
        : "=r"(a) : "l"(p));
    return a;
}
#define SWZ(o) ((o) ^ (((o) >> 3) & 0x70))

#define CP_ASYNC16(s, g) \
    asm volatile("cp.async.cg.shared.global [%0], [%1], 16;" \
                 :: "r"((uint32_t)(s)), "l"(g) : "memory")
#define CP_COMMIT() asm volatile("cp.async.commit_group;" ::: "memory")
template <int N>
__device__ __forceinline__ void cp_wait() {
    asm volatile("cp.async.wait_group %0;" :: "n"(N) : "memory");
}

__device__ __forceinline__ void ldm_x4(uint32_t& r0, uint32_t& r1,
                                       uint32_t& r2, uint32_t& r3, uint32_t a) {
    asm volatile("ldmatrix.sync.aligned.m8n8.x4.shared.b16 {%0,%1,%2,%3}, [%4];"
                 : "=r"(r0), "=r"(r1), "=r"(r2), "=r"(r3) : "r"(a));
}
__device__ __forceinline__ void mma_s8(int* c, const uint32_t* a,
                                       uint32_t b0, uint32_t b1) {
    asm volatile(
        "mma.sync.aligned.m16n8k32.row.col.s32.s8.s8.s32 "
        "{%0,%1,%2,%3}, {%4,%5,%6,%7}, {%8,%9}, {%0,%1,%2,%3};"
        : "+r"(c[0]), "+r"(c[1]), "+r"(c[2]), "+r"(c[3])
        : "r"(a[0]), "r"(a[1]), "r"(a[2]), "r"(a[3]), "r"(b0), "r"(b1));
}

__device__ __forceinline__ float fsigmoid(float x) { return 1.0f / (1.0f + __expf(-x)); }
__device__ __forceinline__ float ftanh(float x)    { return 2.0f / (1.0f + __expf(-2.0f * x)) - 1.0f; }

// quantize v in (-1,1) to two 7-bit limbs: v ~= (q1 + q2/128)/127
__device__ __forceinline__ void quant_limbs(float v, int8_t& q1, int8_t& q2) {
    float s = v * 127.0f;
    float r1 = rintf(s);
    q1 = (int8_t)(int)r1;
    q2 = (int8_t)(int)rintf((s - r1) * 128.0f);
}
__device__ __forceinline__ float clamp1(float v) {
    return fminf(fmaxf(v, -0.999f), 0.999f);
}

// ---------------- init ----------------
__global__ void init_state_kernel() {
    int idx = blockIdx.x * blockDim.x + threadIdx.x;
    if (idx < BATCH * 512) g_H[0][idx] = 0;
    if (idx < BATCH * HID) g_c[idx] = 0.0f;
    if (idx < 4) g_maxu[idx] = 0u;
}

// ---------------- W pack pass1: permute to fp32 temp + |w| max ----------------
template <bool ENC>
__global__ void pack1_kernel(const float* __restrict__ W_ih,
                             const float* __restrict__ W_hh,
                             const float* __restrict__ b) {
    int idx = blockIdx.x * blockDim.x + threadIdx.x;
    if (idx < NG * KP) {
        int n = idx / KP, k = idx % KP;
        int j = n >> 2, g = n & 3;
        int row = g * HID + j;
        float v;
        if (k < HID) v = W_hh[row * HID + k];
        else {
            int kx = k - HID;
            if (ENC) v = W_ih[row * EMB + kx];
            else     v = (kx < INP) ? W_ih[row * INP + kx] : 0.0f;
        }
        g_Wf[idx] = v;
        int slot = (ENC ? 0 : 2) + (k >= HID ? 1 : 0);
        atomicMax(&g_maxu[slot], __float_as_uint(fabsf(v)));
    }
    if (idx < NG) {
        int j = idx >> 2, g = idx & 3;
        (ENC ? g_bias_enc : g_bias_dec)[idx] = b[g * HID + j];
    }
}

// ---------------- W pack pass2: quantize limbs ----------------
template <bool ENC>
__global__ void pack2_kernel() {
    int idx = blockIdx.x * blockDim.x + threadIdx.x;
    if (idx < NG * KP) {
        int n = idx / KP, k = idx % KP;
        int part = (k >= HID) ? 1 : 0;
        float mx = fmaxf(__uint_as_float(g_maxu[(ENC ? 0 : 2) + part]), 1e-20f);
        float S1 = 126.5f / mx;
        float s = g_Wf[idx] * S1;
        float r1 = rintf(s);
        int8_t p1 = (int8_t)(int)r1;
        int8_t p2 = (int8_t)(int)rintf((s - r1) * 128.0f);
        int8_t* W8 = ENC ? g_W8_enc : g_W8_dec;
        W8[n * 640 + k]       = p1;
        W8[n * 640 + 320 + k] = p2;
    }
    if (idx == 0) {
        float mh = fmaxf(__uint_as_float(g_maxu[ENC ? 0 : 2]), 1e-20f);
        float mxx = fmaxf(__uint_as_float(g_maxu[(ENC ? 0 : 2) + 1]), 1e-20f);
        g_cv[(ENC ? 0 : 2) + 0] = mh / (127.0f * 126.5f);          // c_h
        g_cv[(ENC ? 0 : 2) + 1] = 8.0f * mxx / (127.0f * 126.5f);  // c_x (x prescaled /8)
    }
}

// ---------------- embedding: xemb/8 -> limbs ----------------
__global__ void embed_kernel(const float* __restrict__ x,
                             const float* __restrict__ W_emb,
                             const float* __restrict__ b_emb) {
    int idx = blockIdx.x * blockDim.x + threadIdx.x;
    if (idx >= SEQ * BATCH * EMB) return;
    int e  = idx & (EMB - 1);
    int tb = idx >> 6;
    float x0 = x[tb * 2 + 0];
    float x1 = x[tb * 2 + 1];
    float v = b_emb[e] + x0 * W_emb[e * 2 + 0] + x1 * W_emb[e * 2 + 1];
    v = clamp1(v * 0.125f);
    int8_t q1, q2;
    quant_limbs(v, q1, q2);
    g_Xe[tb * 128 + e]      = q1;
    g_Xe[tb * 128 + 64 + e] = q2;
}

// ---------------- decoder first input: x[-1]/8 -> limbs (cols>=INP zero) ----
__global__ void dec_prep_kernel(const float* __restrict__ x) {
    int idx = blockIdx.x * blockDim.x + threadIdx.x;
    if (idx >= BATCH * EMB) return;
    int b = idx >> 6, col = idx & 63;
    float v = (col < INP)
        ? clamp1(x[(size_t)(SEQ - 1) * BATCH * INP + b * INP + col] * 0.125f)
        : 0.0f;
    int8_t q1, q2;
    quant_limbs(v, q1, q2);
    g_Xd[b * 128 + col]      = q1;
    g_Xd[b * 128 + 64 + col] = q2;
}

// ---------------- fused IMMA LSTM step ----------------
// gates[B,1024] = [h|x] @ W^T via int8 limb GEMM, fused cell update.
// CTA 128(M)x64(N), 256 thr, 8 warps (2m x 4n), warp tile 64x16.
template <bool ENC>
__global__ void __launch_bounds__(256, 1)
lstm_step_kernel(int t, int ppi) {
    extern __shared__ __align__(1024) char smem_raw[];
    const uint32_t sb = smem_to_u32(smem_raw);
    const int tid  = threadIdx.x;
    const int warp = tid >> 5, lane = tid & 31;
    const int wm = warp >> 2, wn = warp & 3;
    const int m0 = blockIdx.x * M_CTA, n0 = blockIdx.y * N_CTA;

    const int8_t* __restrict__ Wq  = ENC ? g_W8_enc : g_W8_dec;
    const float* __restrict__ bias = ENC ? g_bias_enc : g_bias_dec;
    const int8_t* __restrict__ hin = g_H[ppi];
    int8_t* __restrict__ hout      = g_H[ppi ^ 1];
    const int8_t* __restrict__ xin =
        ENC ? (g_Xe + (size_t)t * BATCH * 128) : g_Xd;
    const float c_h = g_cv[ENC ? 0 : 2];
    const float c_x = g_cv[ENC ? 1 : 3];

    // ---- issue all 5 chunk loads (chunk 0 = x part, 1..4 = h part) ----
#pragma unroll
    for (int ck = 0; ck < NCHUNK; ck++) {
        const uint32_t sA = sb + ck * STAGE_BYTES;
        const uint32_t sW = sA + A_TILE;
        {   // A: 128 rows x 128B, 2 threads/row, 4 segs each
            const int r = tid >> 1;
            const int8_t* a1b;
            const int8_t* a2b;
            if (ck == 0) {
                a1b = xin + (size_t)(m0 + r) * 128;
                a2b = a1b + 64;
            } else {
                a1b = hin + (size_t)(m0 + r) * 512 + (ck - 1) * 64;
                a2b = a1b + 256;
            }
#pragma unroll
            for (int i = 0; i < 4; i++) {
                const int seg = ((tid & 1) << 2) + i;
                const int8_t* src = (seg < 4) ? (a1b + seg * 16)
                                              : (a2b + (seg - 4) * 16);
                CP_ASYNC16(sA + SWZ(r * 128 + seg * 16), src);
            }
        }
        {   // W: 64 rows x 128B, 4 threads/row, 2 segs each
            const int rw = tid >> 2;
            const int koff = (ck == 0) ? 256 : (ck - 1) * 64;
            const int8_t* wb = Wq + (size_t)(n0 + rw) * 640 + koff;
#pragma unroll
            for (int i = 0; i < 2; i++) {
                const int seg = ((tid & 3) << 1) + i;
                const int8_t* src = (seg < 4) ? (wb + seg * 16)
                                              : (wb + 320 + (seg - 4) * 16);
                CP_ASYNC16(sW + SWZ(rw * 128 + seg * 16), src);
            }
        }
        CP_COMMIT();
    }

    int accM[4][2][4], accX[4][2][4];
#pragma unroll
    for (int a = 0; a < 4; a++)
#pragma unroll
        for (int b = 0; b < 2; b++)
#pragma unroll
            for (int c = 0; c < 4; c++) { accM[a][b][c] = 0; accX[a][b][c] = 0; }

    // ---- per-chunk compute: 2 k32 iters, 3 limb-MMAs per tile ----
    auto compute_chunk = [&](int ck) {
        const uint32_t sA = sb + ck * STAGE_BYTES;
        const uint32_t sW = sA + A_TILE;
#pragma unroll
        for (int k32 = 0; k32 < 2; k32++) {
            uint32_t a1[4][4], a2[4][4];
#pragma unroll
            for (int mt = 0; mt < 4; mt++) {
                const int row = wm * 64 + mt * 16 + (lane & 15);
                const int bc  = k32 * 32 + (lane & 16);
                ldm_x4(a1[mt][0], a1[mt][1], a1[mt][2], a1[mt][3],
                       sA + SWZ(row * 128 + bc));
                ldm_x4(a2[mt][0], a2[mt][1], a2[mt][2], a2[mt][3],
                       sA + SWZ(row * 128 + 64 + bc));
            }
            uint32_t w1[4], w2[4];
            {
                const int row = wn * 16 + (lane & 7) + ((lane & 16) >> 1);
                const int bc  = k32 * 32 + ((lane & 8) << 1);
                ldm_x4(w1[0], w1[1], w1[2], w1[3], sW + SWZ(row * 128 + bc));
                ldm_x4(w2[0], w2[1], w2[2], w2[3], sW + SWZ(row * 128 + 64 + bc));
            }
#pragma unroll
            for (int mt = 0; mt < 4; mt++)
#pragma unroll
                for (int nt = 0; nt < 2; nt++) {
                    mma_s8(accM[mt][nt], a1[mt], w1[2 * nt], w1[2 * nt + 1]);
                    mma_s8(accX[mt][nt], a1[mt], w2[2 * nt], w2[2 * nt + 1]);
                    mma_s8(accX[mt][nt], a2[mt], w1[2 * nt], w1[2 * nt + 1]);
                }
        }
    };

    // ---- phase X (chunk 0) ----
    cp_wait<4>(); __syncthreads();
    compute_chunk(0);
    float fx[4][2][4];
#pragma unroll
    for (int mt = 0; mt < 4; mt++)
#pragma unroll
        for (int nt = 0; nt < 2; nt++)
#pragma unroll
            for (int r = 0; r < 4; r++) {
                fx[mt][nt][r] = fmaf((float)accX[mt][nt][r], 0.0078125f,
                                     (float)accM[mt][nt][r]) * c_x;
                accM[mt][nt][r] = 0; accX[mt][nt][r] = 0;
            }

    // ---- phase H (chunks 1..4) ----
    cp_wait<3>(); __syncthreads(); compute_chunk(1);
    cp_wait<2>(); __syncthreads(); compute_chunk(2);
    cp_wait<1>(); __syncthreads(); compute_chunk(3);
    cp_wait<0>(); __syncthreads(); compute_chunk(4);

    // ---- epilogue ----
    const int odd = lane & 1;
    const int q   = (lane & 2) >> 1;
#pragma unroll
    for (int mt = 0; mt < 4; mt++) {
#pragma unroll
        for (int nt = 0; nt < 2; nt++) {
            float f[4];
#pragma unroll
            for (int r = 0; r < 4; r++)
                f[r] = fmaf((float)accX[mt][nt][r], 0.0078125f,
                            (float)accM[mt][nt][r]) * c_h + fx[mt][nt][r];
            float o0 = __shfl_xor_sync(0xffffffffu, f[0], 1);
            float o1 = __shfl_xor_sync(0xffffffffu, f[1], 1);
            float o2 = __shfl_xor_sync(0xffffffffu, f[2], 1);
            float o3 = __shfl_xor_sync(0xffffffffu, f[3], 1);
            float gi, gf, gg, go;
            int mrow;
            if (!odd) {
                gi = f[0]; gf = f[1]; gg = o0; go = o1;
                mrow = m0 + wm * 64 + mt * 16 + (lane >> 2);
            } else {
                gi = o2; gf = o3; gg = f[2]; go = f[3];
                mrow = m0 + wm * 64 + mt * 16 + (lane >> 2) + 8;
            }
            const int nb = n0 + wn * 16 + nt * 8 + q * 4;
            const float4 bv = *(const float4*)&bias[nb];
            gi += bv.x; gf += bv.y; gg += bv.z; go += bv.w;
            const int j = nb >> 2;
            const size_t cidx = (size_t)mrow * HID + j;
            float cold = g_c[cidx];
            float cn = fsigmoid(gf) * cold + fsigmoid(gi) * ftanh(gg);
            g_c[cidx] = cn;
            float hn = fsigmoid(go) * ftanh(cn);
            int8_t q1, q2;
            quant_limbs(hn, q1, q2);
            hout[(size_t)mrow * 512 + j]       = q1;
            hout[(size_t)mrow * 512 + 256 + j] = q2;
        }
    }
}

// ---------------- decoder output + next-step input limbs ----------------
__global__ void out_kernel(int pp, const float* __restrict__ W_out,
                           const float* __restrict__ b_out,
                           float* __restrict__ out) {
    int gw   = (blockIdx.x * blockDim.x + threadIdx.x) >> 5;
    int lane = threadIdx.x & 31;
    if (gw >= BATCH) return;
    const int8_t* hr = g_H[pp] + (size_t)gw * 512;
    float s0 = 0.0f, s1 = 0.0f;
#pragma unroll
    for (int k = lane; k < HID; k += 32) {
        float hv = ((float)hr[k] + (float)hr[256 + k] * 0.0078125f) * (1.0f / 127.0f);
        s0 += hv * W_out[k];
        s1 += hv * W_out[HID + k];
    }
#pragma unroll
    for (int off = 16; off > 0; off >>= 1) {
        s0 += __shfl_down_sync(0xffffffffu, s0, off);
        s1 += __shfl_down_sync(0xffffffffu, s1, off);
    }
    if (lane == 0) {
        float o0 = s0 + b_out[0];
        float o1 = s1 + b_out[1];
        out[gw * 2 + 0] = o0;
        out[gw * 2 + 1] = o1;
        int8_t q1, q2;
        quant_limbs(clamp1(o0 * 0.125f), q1, q2);
        g_Xd[gw * 128 + 0]  = q1;
        g_Xd[gw * 128 + 64] = q2;
        quant_limbs(clamp1(o1 * 0.125f), q1, q2);
        g_Xd[gw * 128 + 1]  = q1;
        g_Xd[gw * 128 + 65] = q2;
    }
}

// ---------------- launch ----------------
extern "C" void kernel_launch(void* const* d_in, const int* in_sizes, int n_in,
                              void* d_out, int out_size) {
    const float* x        = (const float*)d_in[0];
    const float* W_emb    = (const float*)d_in[1];
    const float* b_emb    = (const float*)d_in[2];
    const float* W_ih_enc = (const float*)d_in[3];
    const float* W_hh_enc = (const float*)d_in[4];
    const float* b_enc    = (const float*)d_in[5];
    const float* W_ih_dec = (const float*)d_in[6];
    const float* W_hh_dec = (const float*)d_in[7];
    const float* b_dec    = (const float*)d_in[8];
    const float* W_out    = (const float*)d_in[9];
    const float* b_out    = (const float*)d_in[10];
    float* out = (float*)d_out;

    cudaFuncSetAttribute(lstm_step_kernel<true>,
                         cudaFuncAttributeMaxDynamicSharedMemorySize, SMEM_DYN_TOTAL);
    cudaFuncSetAttribute(lstm_step_kernel<false>,
                         cudaFuncAttributeMaxDynamicSharedMemorySize, SMEM_DYN_TOTAL);

    init_state_kernel<<<(BATCH * 512 + 255) / 256, 256>>>();
    pack1_kernel<true><<<(NG * KP + 255) / 256, 256>>>(W_ih_enc, W_hh_enc, b_enc);
    pack2_kernel<true><<<(NG * KP + 255) / 256, 256>>>();
    pack1_kernel<false><<<(NG * KP + 255) / 256, 256>>>(W_ih_dec, W_hh_dec, b_dec);
    pack2_kernel<false><<<(NG * KP + 255) / 256, 256>>>();
    embed_kernel<<<(SEQ * BATCH * EMB + 255) / 256, 256>>>(x, W_emb, b_emb);
    dec_prep_kernel<<<(BATCH * EMB + 255) / 256, 256>>>(x);

    dim3 grid(BATCH / M_CTA, NG / N_CTA);   // (128, 16)
    int pp = 0;

    for (int t = 0; t < SEQ; t++) {
        lstm_step_kernel<true><<<grid, 256, SMEM_DYN_TOTAL>>>(t, pp);
        pp ^= 1;
    }
    for (int t = 0; t < TLEN; t++) {
        lstm_step_kernel<false><<<grid, 256, SMEM_DYN_TOTAL>>>(0, pp);
        pp ^= 1;
        out_kernel<<<(BATCH * 32) / 256, 256>>>(pp, W_out, b_out,
                                                out + (size_t)t * BATCH * INP);
    }
}

// round 5
// speedup vs baseline: 2.3794x; 2.3794x over previous
#include <cuda_runtime.h>
#include <cuda_bf16.h>
#include <cstdint>

#define SEQ   20
#define BATCH 16384
#define INP   2
#define HID   256
#define EMB   64
#define TLEN  30
#define NG    1024          /* 4*HID */
#define KP    320           /* per-part K: 256 h + 64 x */
#define KTOT  960           /* [Ah|Ah|Al] x [Wh|Wl|Wh] */
#define KC    64
#define NCH   15

#define M_CTA  128
#define N_CTA  128
#define NSTAGE 3
#define A_TILE 16384        /* 64 k-rows x 128 m-cols x 2B (row pitch 256B) */
#define B_TILE 16384        /* 128 n-rows x 64 k x 2B (row pitch 128B) */
#define STAGE_BYTES (A_TILE + B_TILE)         /* 32KB */
#define SMEM_DYN_TOTAL (NSTAGE * STAGE_BYTES) /* 96KB */

// ---------------- device scratch (all state [feature][batch]) ----------------
__device__ __nv_bfloat16 g_Wt_enc[NG * KTOT];   // [n][960]
__device__ __nv_bfloat16 g_Wt_dec[NG * KTOT];
__device__ float g_bias_enc[NG];
__device__ float g_bias_dec[NG];
__device__ __nv_bfloat16 g_Hh[2][HID * BATCH];  // [j][b]
__device__ __nv_bfloat16 g_Hl[2][HID * BATCH];
__device__ float g_c[HID * BATCH];              // [j][b]
__device__ __nv_bfloat16 g_Xh_enc[SEQ * EMB * BATCH];  // [(t*64+e)][b]
__device__ __nv_bfloat16 g_Xl_enc[SEQ * EMB * BATCH];
__device__ __nv_bfloat16 g_Xdh[EMB * BATCH];    // [e][b]
__device__ __nv_bfloat16 g_Xdl[EMB * BATCH];

// ---------------- helpers ----------------
__device__ __forceinline__ uint32_t smem_to_u32(const void* p) {
    uint32_t a;
    asm("{ .reg .u64 t; cvta.to.shared.u64 t, %1; cvt.u32.u64 %0, t; }"
        : "=r"(a) : "l"(p));
    return a;
}
#define SWZ(o) ((o) ^ (((o) >> 3) & 0x70))
/* A tile swizzle: k-row kr, 16B-column c16 (0..15) */
#define SWZA(kr, c16) ((kr) * 256 + (((c16) ^ ((kr) & 7)) << 4))

#define CP_ASYNC16(s, g) \
    asm volatile("cp.async.cg.shared.global [%0], [%1], 16;" \
                 :: "r"((uint32_t)(s)), "l"(g) : "memory")
#define CP_COMMIT() asm volatile("cp.async.commit_group;" ::: "memory")
template <int N>
__device__ __forceinline__ void cp_wait() {
    asm volatile("cp.async.wait_group %0;" :: "n"(N) : "memory");
}

__device__ __forceinline__ void ldm_x4(uint32_t* r, uint32_t a) {
    asm volatile("ldmatrix.sync.aligned.m8n8.x4.shared.b16 {%0,%1,%2,%3}, [%4];"
                 : "=r"(r[0]), "=r"(r[1]), "=r"(r[2]), "=r"(r[3]) : "r"(a));
}
__device__ __forceinline__ void ldm_x4_trans(uint32_t* r, uint32_t a) {
    asm volatile("ldmatrix.sync.aligned.m8n8.x4.trans.shared.b16 {%0,%1,%2,%3}, [%4];"
                 : "=r"(r[0]), "=r"(r[1]), "=r"(r[2]), "=r"(r[3]) : "r"(a));
}
__device__ __forceinline__ void mma_bf16(float* c, const uint32_t* a,
                                         uint32_t b0, uint32_t b1) {
    asm volatile(
        "mma.sync.aligned.m16n8k16.row.col.f32.bf16.bf16.f32 "
        "{%0,%1,%2,%3}, {%4,%5,%6,%7}, {%8,%9}, {%0,%1,%2,%3};"
        : "+f"(c[0]), "+f"(c[1]), "+f"(c[2]), "+f"(c[3])
        : "r"(a[0]), "r"(a[1]), "r"(a[2]), "r"(a[3]), "r"(b0), "r"(b1));
}

__device__ __forceinline__ float fsigmoid(float x) { return 1.0f / (1.0f + __expf(-x)); }
__device__ __forceinline__ float ftanh(float x)    { return 2.0f / (1.0f + __expf(-2.0f * x)) - 1.0f; }

// ---------------- pack: W' = [Wh | Wl | Wh], n-major ----------------
template <bool ENC>
__global__ void pack_kernel(const float* __restrict__ W_ih,
                            const float* __restrict__ W_hh,
                            const float* __restrict__ b) {
    int idx = blockIdx.x * blockDim.x + threadIdx.x;
    if (idx < NG * KTOT) {
        int n = idx / KTOT, kk = idx % KTOT;
        int p = kk / KP, k = kk % KP;
        int j = n >> 2, g = n & 3;
        int row = g * HID + j;
        float v;
        if (k < HID) v = W_hh[row * HID + k];
        else {
            int kx = k - HID;
            if (ENC) v = W_ih[row * EMB + kx];
            else     v = (kx < INP) ? W_ih[row * INP + kx] : 0.0f;
        }
        __nv_bfloat16 hi = __float2bfloat16(v);
        __nv_bfloat16 ov = (p == 1) ? __float2bfloat16(v - __bfloat162float(hi)) : hi;
        (ENC ? g_Wt_enc : g_Wt_dec)[idx] = ov;
    }
    if (idx < NG) {
        int j = idx >> 2, g = idx & 3;
        (ENC ? g_bias_enc : g_bias_dec)[idx] = b[g * HID + j];
    }
}

__global__ void init_state_kernel() {
    int idx = blockIdx.x * blockDim.x + threadIdx.x;
    if (idx < HID * BATCH) {
        g_Hh[0][idx] = __float2bfloat16(0.0f);
        g_Hl[0][idx] = __float2bfloat16(0.0f);
        g_c[idx]     = 0.0f;
    }
}

// ---------------- embedding -> [e][b] split bf16 ----------------
__global__ void embed_kernel(const float* __restrict__ x,
                             const float* __restrict__ W_emb,
                             const float* __restrict__ b_emb) {
    int idx = blockIdx.x * blockDim.x + threadIdx.x;
    if (idx >= SEQ * EMB * BATCH) return;
    int b  = idx & (BATCH - 1);
    int te = idx >> 14;
    int e  = te & (EMB - 1);
    int t  = te >> 6;
    float x0 = x[((size_t)t * BATCH + b) * 2 + 0];
    float x1 = x[((size_t)t * BATCH + b) * 2 + 1];
    float v = b_emb[e] + x0 * W_emb[e * 2 + 0] + x1 * W_emb[e * 2 + 1];
    __nv_bfloat16 hi = __float2bfloat16(v);
    g_Xh_enc[idx] = hi;
    g_Xl_enc[idx] = __float2bfloat16(v - __bfloat162float(hi));
}

// ---------------- decoder first input [e][b] ----------------
__global__ void dec_prep_kernel(const float* __restrict__ x) {
    int idx = blockIdx.x * blockDim.x + threadIdx.x;
    if (idx >= EMB * BATCH) return;
    int b = idx & (BATCH - 1);
    int e = idx >> 14;
    float v = (e < INP) ? x[(size_t)(SEQ - 1) * BATCH * INP + b * INP + e] : 0.0f;
    __nv_bfloat16 hi = __float2bfloat16(v);
    g_Xdh[idx] = hi;
    g_Xdl[idx] = __float2bfloat16(v - __bfloat162float(hi));
}

// ---------------- fused HMMA LSTM step ----------------
// CTA 128(M batch)x128(N gates), 256 thr, 8 warps (2m x 4n), warp 64x32.
// A tile k-major [64][128] via ldmatrix.trans; B tile n-major [128][64].
template <bool ENC>
__global__ void __launch_bounds__(256, 2)
lstm_step_kernel(int t, int ppi) {
    extern __shared__ __align__(1024) char smem_raw[];
    const uint32_t sb = smem_to_u32(smem_raw);
    const int tid  = threadIdx.x;
    const int warp = tid >> 5, lane = tid & 31;
    const int wm = warp >> 2, wn = warp & 3;
    const int m0 = blockIdx.x * M_CTA, n0 = blockIdx.y * N_CTA;

    const __nv_bfloat16* __restrict__ Wt = ENC ? g_Wt_enc : g_Wt_dec;
    const float* __restrict__ bias       = ENC ? g_bias_enc : g_bias_dec;
    const __nv_bfloat16* __restrict__ hh = g_Hh[ppi];
    const __nv_bfloat16* __restrict__ hl = g_Hl[ppi];
    __nv_bfloat16* __restrict__ hho      = g_Hh[ppi ^ 1];
    __nv_bfloat16* __restrict__ hlo      = g_Hl[ppi ^ 1];
    const __nv_bfloat16* __restrict__ xh =
        ENC ? (g_Xh_enc + (size_t)t * EMB * BATCH) : g_Xdh;
    const __nv_bfloat16* __restrict__ xl =
        ENC ? (g_Xl_enc + (size_t)t * EMB * BATCH) : g_Xdl;

    // ---- chunk loader ----
    auto load_chunk = [&](int ck, int st) {
        const uint32_t sA = sb + st * STAGE_BYTES;
        const uint32_t sW = sA + A_TILE;
        const int p = (ck < 5) ? 0 : (ck < 10 ? 1 : 2);
        const int off = ck - p * 5;
        const __nv_bfloat16* ab;
        if (off == 4) ab = (p < 2) ? xh : xl;
        else          ab = ((p < 2) ? hh : hl) + (size_t)(off * KC) * BATCH;
        // A: 64 rows x 256B; thread t: row t>>2, 4x16B cols
        {
            const int kr = tid >> 2;
            const __nv_bfloat16* g = ab + (size_t)kr * BATCH + m0;
#pragma unroll
            for (int i = 0; i < 4; i++) {
                const int c16 = (tid & 3) * 4 + i;
                CP_ASYNC16(sA + SWZA(kr, c16), g + c16 * 8);
            }
        }
        // W: 128 rows x 128B; thread t: row t>>1, 4x16B segs
        {
            const int rw = tid >> 1;
            const __nv_bfloat16* gw = Wt + (size_t)(n0 + rw) * KTOT + ck * KC;
#pragma unroll
            for (int i = 0; i < 4; i++) {
                const int seg = (tid & 1) * 4 + i;
                CP_ASYNC16(sW + SWZ(rw * 128 + seg * 16), gw + seg * 8);
            }
        }
    };

    float acc[4][4][4];
#pragma unroll
    for (int a = 0; a < 4; a++)
#pragma unroll
        for (int b = 0; b < 4; b++)
#pragma unroll
            for (int c = 0; c < 4; c++) acc[a][b][c] = 0.0f;

    load_chunk(0, 0); CP_COMMIT();
    load_chunk(1, 1); CP_COMMIT();

    for (int ck = 0; ck < NCH; ck++) {
        const int st = ck % NSTAGE;
        cp_wait<1>();
        __syncthreads();
        if (ck + 2 < NCH) load_chunk(ck + 2, (ck + 2) % NSTAGE);
        CP_COMMIT();

        const uint32_t sA = sb + st * STAGE_BYTES;
        const uint32_t sW = sA + A_TILE;
#pragma unroll
        for (int k16 = 0; k16 < 4; k16++) {
            uint32_t afr[4][4];
            const int kr = k16 * 16 + (lane & 7) + ((lane & 16) >> 1);
#pragma unroll
            for (int mt = 0; mt < 4; mt++) {
                const int mc = wm * 64 + mt * 16 + (lane & 8);
                ldm_x4_trans(afr[mt], sA + SWZA(kr, mc >> 3));
            }
            uint32_t bfr[2][4];
#pragma unroll
            for (int p = 0; p < 2; p++) {
                const int row  = wn * 32 + p * 16 + (lane & 7) + ((lane & 16) >> 1);
                const int kcol = k16 * 16 + ((lane & 8) ? 8 : 0);
                ldm_x4(bfr[p], sW + SWZ(row * 128 + kcol * 2));
            }
#pragma unroll
            for (int mt = 0; mt < 4; mt++)
#pragma unroll
                for (int nt = 0; nt < 4; nt++)
                    mma_bf16(acc[mt][nt], afr[mt],
                             bfr[nt >> 1][(nt & 1) * 2],
                             bfr[nt >> 1][(nt & 1) * 2 + 1]);
        }
    }

    // ---- epilogue: coalesced against [j][b] state ----
    const int odd = lane & 1;
    const int q   = (lane & 2) >> 1;
#pragma unroll
    for (int mt = 0; mt < 4; mt++) {
#pragma unroll
        for (int nt = 0; nt < 4; nt++) {
            float o0 = __shfl_xor_sync(0xffffffffu, acc[mt][nt][0], 1);
            float o1 = __shfl_xor_sync(0xffffffffu, acc[mt][nt][1], 1);
            float o2 = __shfl_xor_sync(0xffffffffu, acc[mt][nt][2], 1);
            float o3 = __shfl_xor_sync(0xffffffffu, acc[mt][nt][3], 1);
            float gi, gf, gg, go;
            int mrow;
            if (!odd) {
                gi = acc[mt][nt][0]; gf = acc[mt][nt][1];
                gg = o0;             go = o1;
                mrow = m0 + wm * 64 + mt * 16 + (lane >> 2);
            } else {
                gi = o2;             gf = o3;
                gg = acc[mt][nt][2]; go = acc[mt][nt][3];
                mrow = m0 + wm * 64 + mt * 16 + (lane >> 2) + 8;
            }
            const int nb = n0 + wn * 32 + nt * 8 + q * 4;
            const float4 bv = *(const float4*)&bias[nb];
            gi += bv.x; gf += bv.y; gg += bv.z; go += bv.w;
            const int j = nb >> 2;
            const size_t sidx = (size_t)j * BATCH + mrow;
            float cold = g_c[sidx];
            float cn = fsigmoid(gf) * cold + fsigmoid(gi) * ftanh(gg);
            g_c[sidx] = cn;
            float hn = fsigmoid(go) * ftanh(cn);
            __nv_bfloat16 hb = __float2bfloat16(hn);
            hho[sidx] = hb;
            hlo[sidx] = __float2bfloat16(hn - __bfloat162float(hb));
        }
    }
}

// ---------------- decoder output: thread-per-batch-row ----------------
__global__ void out_kernel(int pp, const float* __restrict__ W_out,
                           const float* __restrict__ b_out,
                           float* __restrict__ out) {
    __shared__ float wo0[HID], wo1[HID];
    const int tid = threadIdx.x;
    if (tid < HID) { wo0[tid] = W_out[tid]; wo1[tid] = W_out[HID + tid]; }
    __syncthreads();
    const int b = blockIdx.x * blockDim.x + tid;
    const __nv_bfloat16* hh = g_Hh[pp];
    const __nv_bfloat16* hl = g_Hl[pp];
    float s0 = 0.0f, s1 = 0.0f;
#pragma unroll 8
    for (int j = 0; j < HID; j++) {
        const size_t idx = (size_t)j * BATCH + b;
        float hv = __bfloat162float(hh[idx]) + __bfloat162float(hl[idx]);
        s0 = fmaf(hv, wo0[j], s0);
        s1 = fmaf(hv, wo1[j], s1);
    }
    float o0 = s0 + b_out[0];
    float o1 = s1 + b_out[1];
    out[b * 2 + 0] = o0;
    out[b * 2 + 1] = o1;
    __nv_bfloat16 h0 = __float2bfloat16(o0);
    __nv_bfloat16 h1 = __float2bfloat16(o1);
    g_Xdh[b]         = h0;
    g_Xdh[BATCH + b] = h1;
    g_Xdl[b]         = __float2bfloat16(o0 - __bfloat162float(h0));
    g_Xdl[BATCH + b] = __float2bfloat16(o1 - __bfloat162float(h1));
}

// ---------------- launch ----------------
extern "C" void kernel_launch(void* const* d_in, const int* in_sizes, int n_in,
                              void* d_out, int out_size) {
    const float* x        = (const float*)d_in[0];
    const float* W_emb    = (const float*)d_in[1];
    const float* b_emb    = (const float*)d_in[2];
    const float* W_ih_enc = (const float*)d_in[3];
    const float* W_hh_enc = (const float*)d_in[4];
    const float* b_enc    = (const float*)d_in[5];
    const float* W_ih_dec = (const float*)d_in[6];
    const float* W_hh_dec = (const float*)d_in[7];
    const float* b_dec    = (const float*)d_in[8];
    const float* W_out    = (const float*)d_in[9];
    const float* b_out    = (const float*)d_in[10];
    float* out = (float*)d_out;

    cudaFuncSetAttribute(lstm_step_kernel<true>,
                         cudaFuncAttributeMaxDynamicSharedMemorySize, SMEM_DYN_TOTAL);
    cudaFuncSetAttribute(lstm_step_kernel<false>,
                         cudaFuncAttributeMaxDynamicSharedMemorySize, SMEM_DYN_TOTAL);

    pack_kernel<true><<<(NG * KTOT + 255) / 256, 256>>>(W_ih_enc, W_hh_enc, b_enc);
    pack_kernel<false><<<(NG * KTOT + 255) / 256, 256>>>(W_ih_dec, W_hh_dec, b_dec);
    init_state_kernel<<<(HID * BATCH + 255) / 256, 256>>>();
    embed_kernel<<<(SEQ * EMB * BATCH + 255) / 256, 256>>>(x, W_emb, b_emb);
    dec_prep_kernel<<<(EMB * BATCH + 255) / 256, 256>>>(x);

    dim3 grid(BATCH / M_CTA, NG / N_CTA);   // (128, 8)
    int pp = 0;

    for (int t = 0; t < SEQ; t++) {
        lstm_step_kernel<true><<<grid, 256, SMEM_DYN_TOTAL>>>(t, pp);
        pp ^= 1;
    }
    for (int t = 0; t < TLEN; t++) {
        lstm_step_kernel<false><<<grid, 256, SMEM_DYN_TOTAL>>>(0, pp);
        pp ^= 1;
        out_kernel<<<BATCH / 256, 256>>>(pp, W_out, b_out,
                                         out + (size_t)t * BATCH * INP);
    }
}

// round 6
// speedup vs baseline: 2.9177x; 1.2262x over previous
#include <cuda_runtime.h>
#include <cuda_bf16.h>
#include <cstdint>

#define SEQ   20
#define BATCH 16384
#define INP   2
#define HID   256
#define EMB   64
#define TLEN  30
#define NG    1024          /* 4*HID */
#define KP    320           /* per-part K: 256 h + 64 x */
#define KTOT  960           /* [Ah|Ah|Al] x [Wh|Wl|Wh] */
#define KC    64

#define M_CTA  128
#define N_CTA  128
#define NSTAGE 3
#define A_TILE 16384        /* 64 k-rows x 128 m-cols x 2B (row pitch 256B) */
#define B_TILE 16384        /* 128 n-rows x 64 k x 2B (row pitch 128B) */
#define STAGE_BYTES (A_TILE + B_TILE)         /* 32KB */
#define SMEM_DYN_TOTAL (NSTAGE * STAGE_BYTES) /* 96KB */

/* MODE: 0 = encoder full (NCH 15), 1 = encoder t=0, h=0 (NCH 3),
         2 = decoder, x via epilogue (NCH 12) */

// ---------------- device scratch (all state [feature][batch]) ----------------
__device__ __nv_bfloat16 g_Wt_enc[NG * KTOT];   // [n][960]
__device__ __nv_bfloat16 g_Wt_dec[NG * KTOT];
__device__ float g_Wxd[NG * 2];                 // decoder W_ih packed [n][2] fp32
__device__ float g_bias_enc[NG];
__device__ float g_bias_dec[NG];
__device__ __nv_bfloat16 g_Hh[2][HID * BATCH];  // [j][b]
__device__ __nv_bfloat16 g_Hl[2][HID * BATCH];
__device__ float g_c[HID * BATCH];              // [j][b]
__device__ __nv_bfloat16 g_Xh_enc[SEQ * EMB * BATCH];  // [(t*64+e)][b]
__device__ __nv_bfloat16 g_Xl_enc[SEQ * EMB * BATCH];

// ---------------- helpers ----------------
__device__ __forceinline__ uint32_t smem_to_u32(const void* p) {
    uint32_t a;
    asm("{ .reg .u64 t; cvta.to.shared.u64 t, %1; cvt.u32.u64 %0, t; }"
        : "=r"(a) : "l"(p));
    return a;
}
#define SWZ(o) ((o) ^ (((o) >> 3) & 0x70))
#define SWZA(kr, c16) ((kr) * 256 + (((c16) ^ ((kr) & 7)) << 4))

#define CP_ASYNC16(s, g) \
    asm volatile("cp.async.cg.shared.global [%0], [%1], 16;" \
                 :: "r"((uint32_t)(s)), "l"(g) : "memory")
#define CP_COMMIT() asm volatile("cp.async.commit_group;" ::: "memory")
template <int N>
__device__ __forceinline__ void cp_wait() {
    asm volatile("cp.async.wait_group %0;" :: "n"(N) : "memory");
}

__device__ __forceinline__ void ldm_x4(uint32_t* r, uint32_t a) {
    asm volatile("ldmatrix.sync.aligned.m8n8.x4.shared.b16 {%0,%1,%2,%3}, [%4];"
                 : "=r"(r[0]), "=r"(r[1]), "=r"(r[2]), "=r"(r[3]) : "r"(a));
}
__device__ __forceinline__ void ldm_x4_trans(uint32_t* r, uint32_t a) {
    asm volatile("ldmatrix.sync.aligned.m8n8.x4.trans.shared.b16 {%0,%1,%2,%3}, [%4];"
                 : "=r"(r[0]), "=r"(r[1]), "=r"(r[2]), "=r"(r[3]) : "r"(a));
}
__device__ __forceinline__ void mma_bf16(float* c, const uint32_t* a,
                                         uint32_t b0, uint32_t b1) {
    asm volatile(
        "mma.sync.aligned.m16n8k16.row.col.f32.bf16.bf16.f32 "
        "{%0,%1,%2,%3}, {%4,%5,%6,%7}, {%8,%9}, {%0,%1,%2,%3};"
        : "+f"(c[0]), "+f"(c[1]), "+f"(c[2]), "+f"(c[3])
        : "r"(a[0]), "r"(a[1]), "r"(a[2]), "r"(a[3]), "r"(b0), "r"(b1));
}

__device__ __forceinline__ float fsigmoid(float x) { return 1.0f / (1.0f + __expf(-x)); }
__device__ __forceinline__ float ftanh(float x)    { return 2.0f / (1.0f + __expf(-2.0f * x)) - 1.0f; }

// ---------------- pack: W' = [Wh | Wl | Wh], n-major ----------------
template <bool ENC>
__global__ void pack_kernel(const float* __restrict__ W_ih,
                            const float* __restrict__ W_hh,
                            const float* __restrict__ b) {
    int idx = blockIdx.x * blockDim.x + threadIdx.x;
    if (idx < NG * KTOT) {
        int n = idx / KTOT, kk = idx % KTOT;
        int p = kk / KP, k = kk % KP;
        int j = n >> 2, g = n & 3;
        int row = g * HID + j;
        float v;
        if (k < HID) v = W_hh[row * HID + k];
        else {
            int kx = k - HID;
            if (ENC) v = W_ih[row * EMB + kx];
            else     v = (kx < INP) ? W_ih[row * INP + kx] : 0.0f;
        }
        __nv_bfloat16 hi = __float2bfloat16(v);
        __nv_bfloat16 ov = (p == 1) ? __float2bfloat16(v - __bfloat162float(hi)) : hi;
        (ENC ? g_Wt_enc : g_Wt_dec)[idx] = ov;
    }
    if (idx < NG) {
        int j = idx >> 2, g = idx & 3;
        (ENC ? g_bias_enc : g_bias_dec)[idx] = b[g * HID + j];
    }
    if (!ENC && idx < NG * 2) {
        int n = idx >> 1, k = idx & 1;
        int j = n >> 2, g = n & 3;
        g_Wxd[idx] = W_ih[(g * HID + j) * INP + k];
    }
}

__global__ void init_state_kernel() {
    int idx = blockIdx.x * blockDim.x + threadIdx.x;
    if (idx < HID * BATCH) g_c[idx] = 0.0f;
}

__global__ void init_out_kernel(const float* __restrict__ b_out,
                                float* __restrict__ out) {
    int idx = blockIdx.x * blockDim.x + threadIdx.x;
    if (idx < TLEN * BATCH * 2) out[idx] = b_out[idx & 1];
}

// ---------------- embedding -> [e][b] split bf16 ----------------
__global__ void embed_kernel(const float* __restrict__ x,
                             const float* __restrict__ W_emb,
                             const float* __restrict__ b_emb) {
    int idx = blockIdx.x * blockDim.x + threadIdx.x;
    if (idx >= SEQ * EMB * BATCH) return;
    int b  = idx & (BATCH - 1);
    int te = idx >> 14;
    int e  = te & (EMB - 1);
    int t  = te >> 6;
    float x0 = x[((size_t)t * BATCH + b) * 2 + 0];
    float x1 = x[((size_t)t * BATCH + b) * 2 + 1];
    float v = b_emb[e] + x0 * W_emb[e * 2 + 0] + x1 * W_emb[e * 2 + 1];
    __nv_bfloat16 hi = __float2bfloat16(v);
    g_Xh_enc[idx] = hi;
    g_Xl_enc[idx] = __float2bfloat16(v - __bfloat162float(hi));
}

// ---------------- fused HMMA LSTM step ----------------
// CTA 128(M batch)x128(N gates), 256 thr, 8 warps (2m x 4n), warp 64x32.
template <int MODE>
__global__ void __launch_bounds__(256, 2)
lstm_step_kernel(int t, int ppi,
                 const float* __restrict__ prev,   // MODE 2: [b][2] fp32
                 float* __restrict__ outp,         // MODE 2: out[t] [b][2]
                 const float* __restrict__ Wout) { // MODE 2: [2][256]
    constexpr int NCH = (MODE == 0) ? 15 : (MODE == 1 ? 3 : 12);
    constexpr bool ENC = (MODE != 2);
    extern __shared__ __align__(1024) char smem_raw[];
    const uint32_t sb = smem_to_u32(smem_raw);
    const int tid  = threadIdx.x;
    const int warp = tid >> 5, lane = tid & 31;
    const int wm = warp >> 2, wn = warp & 3;
    const int m0 = blockIdx.x * M_CTA, n0 = blockIdx.y * N_CTA;

    const __nv_bfloat16* __restrict__ Wt = ENC ? g_Wt_enc : g_Wt_dec;
    const float* __restrict__ bias       = ENC ? g_bias_enc : g_bias_dec;
    const __nv_bfloat16* __restrict__ hh = g_Hh[ppi];
    const __nv_bfloat16* __restrict__ hl = g_Hl[ppi];
    __nv_bfloat16* __restrict__ hho      = g_Hh[ppi ^ 1];
    __nv_bfloat16* __restrict__ hlo      = g_Hl[ppi ^ 1];
    const __nv_bfloat16* __restrict__ xh = g_Xh_enc + (size_t)t * EMB * BATCH;
    const __nv_bfloat16* __restrict__ xl = g_Xl_enc + (size_t)t * EMB * BATCH;

    // ---- chunk loader ----
    auto load_chunk = [&](int ck, int st) {
        const uint32_t sA = sb + st * STAGE_BYTES;
        const uint32_t sW = sA + A_TILE;
        const __nv_bfloat16* ab;
        int woff;
        if (MODE == 0) {
            const int p = (ck < 5) ? 0 : (ck < 10 ? 1 : 2);
            const int off = ck - p * 5;
            woff = p * KP + off * KC;
            if (off == 4) ab = (p < 2) ? xh : xl;
            else          ab = ((p < 2) ? hh : hl) + (size_t)(off * KC) * BATCH;
        } else if (MODE == 1) {
            woff = ck * KP + 256;
            ab = (ck == 2) ? xl : xh;
        } else {
            const int p = ck >> 2;
            const int off = ck & 3;
            woff = p * KP + off * KC;
            ab = ((p < 2) ? hh : hl) + (size_t)(off * KC) * BATCH;
        }
        // A: 64 rows x 256B; thread t: row t>>2, 4x16B cols
        {
            const int kr = tid >> 2;
            const __nv_bfloat16* g = ab + (size_t)kr * BATCH + m0;
#pragma unroll
            for (int i = 0; i < 4; i++) {
                const int c16 = (tid & 3) * 4 + i;
                CP_ASYNC16(sA + SWZA(kr, c16), g + c16 * 8);
            }
        }
        // W: 128 rows x 128B; thread t: row t>>1, 4x16B segs
        {
            const int rw = tid >> 1;
            const __nv_bfloat16* gw = Wt + (size_t)(n0 + rw) * KTOT + woff;
#pragma unroll
            for (int i = 0; i < 4; i++) {
                const int seg = (tid & 1) * 4 + i;
                CP_ASYNC16(sW + SWZ(rw * 128 + seg * 16), gw + seg * 8);
            }
        }
    };

    float acc[4][4][4];
#pragma unroll
    for (int a = 0; a < 4; a++)
#pragma unroll
        for (int b = 0; b < 4; b++)
#pragma unroll
            for (int c = 0; c < 4; c++) acc[a][b][c] = 0.0f;

    load_chunk(0, 0); CP_COMMIT();
    load_chunk(1, 1); CP_COMMIT();

    for (int ck = 0; ck < NCH; ck++) {
        const int st = ck % NSTAGE;
        cp_wait<1>();
        __syncthreads();
        if (ck + 2 < NCH) load_chunk(ck + 2, (ck + 2) % NSTAGE);
        CP_COMMIT();

        const uint32_t sA = sb + st * STAGE_BYTES;
        const uint32_t sW = sA + A_TILE;
#pragma unroll
        for (int k16 = 0; k16 < 4; k16++) {
            uint32_t afr[4][4];
            const int kr = k16 * 16 + (lane & 7) + ((lane & 16) >> 1);
#pragma unroll
            for (int mt = 0; mt < 4; mt++) {
                const int mc = wm * 64 + mt * 16 + (lane & 8);
                ldm_x4_trans(afr[mt], sA + SWZA(kr, mc >> 3));
            }
            uint32_t bfr[2][4];
#pragma unroll
            for (int p = 0; p < 2; p++) {
                const int row  = wn * 32 + p * 16 + (lane & 7) + ((lane & 16) >> 1);
                const int kcol = k16 * 16 + ((lane & 8) ? 8 : 0);
                ldm_x4(bfr[p], sW + SWZ(row * 128 + kcol * 2));
            }
#pragma unroll
            for (int mt = 0; mt < 4; mt++)
#pragma unroll
                for (int nt = 0; nt < 4; nt++)
                    mma_bf16(acc[mt][nt], afr[mt],
                             bfr[nt >> 1][(nt & 1) * 2],
                             bfr[nt >> 1][(nt & 1) * 2 + 1]);
        }
    }

    // ---- epilogue ----
    const int odd = lane & 1;
    const int q   = (lane & 2) >> 1;
    float s0m[4] = {0, 0, 0, 0}, s1m[4] = {0, 0, 0, 0};
    float xv0[4], xv1[4];
    if (MODE == 2) {
#pragma unroll
        for (int mt = 0; mt < 4; mt++) {
            const int mrow = m0 + wm * 64 + mt * 16 + (lane >> 2) + 8 * odd;
            xv0[mt] = prev[mrow * 2 + 0];
            xv1[mt] = prev[mrow * 2 + 1];
        }
    }
#pragma unroll
    for (int nt = 0; nt < 4; nt++) {
        const int nb = n0 + wn * 32 + nt * 8 + q * 4;
        const float4 bv = *(const float4*)&bias[nb];
        const int j = nb >> 2;
        float wx0[4], wx1[4], w_o0 = 0.0f, w_o1 = 0.0f;
        if (MODE == 2) {
#pragma unroll
            for (int r = 0; r < 4; r++) {
                wx0[r] = g_Wxd[(nb + r) * 2 + 0];
                wx1[r] = g_Wxd[(nb + r) * 2 + 1];
            }
            w_o0 = Wout[j];
            w_o1 = Wout[HID + j];
        }
#pragma unroll
        for (int mt = 0; mt < 4; mt++) {
            float o0 = __shfl_xor_sync(0xffffffffu, acc[mt][nt][0], 1);
            float o1 = __shfl_xor_sync(0xffffffffu, acc[mt][nt][1], 1);
            float o2 = __shfl_xor_sync(0xffffffffu, acc[mt][nt][2], 1);
            float o3 = __shfl_xor_sync(0xffffffffu, acc[mt][nt][3], 1);
            float gi, gf, gg, go;
            if (!odd) { gi = acc[mt][nt][0]; gf = acc[mt][nt][1]; gg = o0; go = o1; }
            else      { gi = o2; gf = o3; gg = acc[mt][nt][2]; go = acc[mt][nt][3]; }
            const int mrow = m0 + wm * 64 + mt * 16 + (lane >> 2) + 8 * odd;
            if (MODE == 2) {
                gi = fmaf(xv0[mt], wx0[0], fmaf(xv1[mt], wx1[0], gi));
                gf = fmaf(xv0[mt], wx0[1], fmaf(xv1[mt], wx1[1], gf));
                gg = fmaf(xv0[mt], wx0[2], fmaf(xv1[mt], wx1[2], gg));
                go = fmaf(xv0[mt], wx0[3], fmaf(xv1[mt], wx1[3], go));
            }
            gi += bv.x; gf += bv.y; gg += bv.z; go += bv.w;
            const size_t sidx = (size_t)j * BATCH + mrow;
            float cold = g_c[sidx];
            float cn = fsigmoid(gf) * cold + fsigmoid(gi) * ftanh(gg);
            g_c[sidx] = cn;
            float hn = fsigmoid(go) * ftanh(cn);
            __nv_bfloat16 hb = __float2bfloat16(hn);
            hho[sidx] = hb;
            hlo[sidx] = __float2bfloat16(hn - __bfloat162float(hb));
            if (MODE == 2) {
                s0m[mt] = fmaf(hn, w_o0, s0m[mt]);
                s1m[mt] = fmaf(hn, w_o1, s1m[mt]);
            }
        }
    }

    // ---- MODE 2: reduce out partials and accumulate to out[t] ----
    if (MODE == 2) {
        float* sOut = (float*)smem_raw;   // 128 rows x 2
        __syncthreads();                  // all GEMM smem reads done
        sOut[tid] = 0.0f;
        __syncthreads();
#pragma unroll
        for (int mt = 0; mt < 4; mt++) {
            s0m[mt] += __shfl_xor_sync(0xffffffffu, s0m[mt], 2);
            s1m[mt] += __shfl_xor_sync(0xffffffffu, s1m[mt], 2);
        }
        if (!(lane & 2)) {
#pragma unroll
            for (int mt = 0; mt < 4; mt++) {
                const int r = wm * 64 + mt * 16 + (lane >> 2) + 8 * odd;
                atomicAdd(&sOut[r * 2 + 0], s0m[mt]);
                atomicAdd(&sOut[r * 2 + 1], s1m[mt]);
            }
        }
        __syncthreads();
        atomicAdd(&outp[(size_t)(m0 + (tid >> 1)) * 2 + (tid & 1)], sOut[tid]);
    }
}

// ---------------- launch ----------------
extern "C" void kernel_launch(void* const* d_in, const int* in_sizes, int n_in,
                              void* d_out, int out_size) {
    const float* x        = (const float*)d_in[0];
    const float* W_emb    = (const float*)d_in[1];
    const float* b_emb    = (const float*)d_in[2];
    const float* W_ih_enc = (const float*)d_in[3];
    const float* W_hh_enc = (const float*)d_in[4];
    const float* b_enc    = (const float*)d_in[5];
    const float* W_ih_dec = (const float*)d_in[6];
    const float* W_hh_dec = (const float*)d_in[7];
    const float* b_dec    = (const float*)d_in[8];
    const float* W_out    = (const float*)d_in[9];
    const float* b_out    = (const float*)d_in[10];
    float* out = (float*)d_out;

    cudaFuncSetAttribute(lstm_step_kernel<0>,
                         cudaFuncAttributeMaxDynamicSharedMemorySize, SMEM_DYN_TOTAL);
    cudaFuncSetAttribute(lstm_step_kernel<1>,
                         cudaFuncAttributeMaxDynamicSharedMemorySize, SMEM_DYN_TOTAL);
    cudaFuncSetAttribute(lstm_step_kernel<2>,
                         cudaFuncAttributeMaxDynamicSharedMemorySize, SMEM_DYN_TOTAL);

    pack_kernel<true><<<(NG * KTOT + 255) / 256, 256>>>(W_ih_enc, W_hh_enc, b_enc);
    pack_kernel<false><<<(NG * KTOT + 255) / 256, 256>>>(W_ih_dec, W_hh_dec, b_dec);
    init_state_kernel<<<(HID * BATCH + 255) / 256, 256>>>();
    init_out_kernel<<<(TLEN * BATCH * 2 + 255) / 256, 256>>>(b_out, out);
    embed_kernel<<<(SEQ * EMB * BATCH + 255) / 256, 256>>>(x, W_emb, b_emb);

    dim3 grid(BATCH / M_CTA, NG / N_CTA);   // (128, 8)
    int pp = 0;

    // encoder: t=0 has h=0 -> x-only GEMM
    lstm_step_kernel<1><<<grid, 256, SMEM_DYN_TOTAL>>>(0, pp, nullptr, nullptr, nullptr);
    pp ^= 1;
    for (int t = 1; t < SEQ; t++) {
        lstm_step_kernel<0><<<grid, 256, SMEM_DYN_TOTAL>>>(t, pp, nullptr, nullptr, nullptr);
        pp ^= 1;
    }
    // decoder: x injected in epilogue; out fused via atomics
    for (int t = 0; t < TLEN; t++) {
        const float* prev = (t == 0) ? (x + (size_t)(SEQ - 1) * BATCH * INP)
                                     : (out + (size_t)(t - 1) * BATCH * 2);
        lstm_step_kernel<2><<<grid, 256, SMEM_DYN_TOTAL>>>(
            0, pp, prev, out + (size_t)t * BATCH * 2, W_out);
        pp ^= 1;
    }
}

// round 7
// speedup vs baseline: 3.9152x; 1.3419x over previous
#include <cuda_runtime.h>
#include <cuda_fp16.h>
#include <cstdint>

#define SEQ   20
#define BATCH 16384
#define INP   2
#define HID   256
#define EMB   64
#define TLEN  30
#define NG    1024          /* 4*HID */
#define KC    64

#define M_CTA  128
#define N_CTA  128
#define NSTAGE 3
#define A_TILE 16384        /* 64 k-rows x 128 m-cols x 2B (row pitch 256B) */
#define B_TILE 16384        /* 128 n-rows x 64 k x 2B (row pitch 128B) */
#define STAGE_BYTES (A_TILE + B_TILE)         /* 32KB */
#define SMEM_DYN_TOTAL (NSTAGE * STAGE_BYTES) /* 96KB */

#define INV2048 4.8828125e-4f

/* MODE: 0 = encoder (NCH 10: 5 lo-plane chunks then 5 hi-plane),
         1 = encoder t=0, h=0 (NCH 2: x lo, x hi),
         2 = decoder (NCH 8), x + out-projection fused in epilogue */

// ---------------- device scratch (all state [feature][batch]) ----------------
// enc W': [n][640] = Wl'(h)[256] | Wxl'[64] | Wh(h)[256] | Wxh[64]
// dec W': [n][512] = Wl'(h)[256] | Wh(h)[256]
__device__ __half g_W_enc[NG * 640];
__device__ __half g_W_dec[NG * 512];
__device__ float g_Wxd[NG * 2];                 // decoder W_ih [n][2] fp32
__device__ float g_bias_enc[NG];
__device__ float g_bias_dec[NG];
__device__ __half g_H[2][HID * BATCH];          // [j][b] single fp16 plane
__device__ float g_c[HID * BATCH];              // [j][b]
__device__ __half g_Xe[SEQ * EMB * BATCH];      // [(t*64+e)][b]

// ---------------- helpers ----------------
__device__ __forceinline__ uint32_t smem_to_u32(const void* p) {
    uint32_t a;
    asm("{ .reg .u64 t; cvta.to.shared.u64 t, %1; cvt.u32.u64 %0, t; }"
        : "=r"(a) : "l"(p));
    return a;
}
#define SWZ(o) ((o) ^ (((o) >> 3) & 0x70))
#define SWZA(kr, c16) ((kr) * 256 + (((c16) ^ ((kr) & 7)) << 4))

#define CP_ASYNC16(s, g) \
    asm volatile("cp.async.cg.shared.global [%0], [%1], 16;" \
                 :: "r"((uint32_t)(s)), "l"(g) : "memory")
#define CP_COMMIT() asm volatile("cp.async.commit_group;" ::: "memory")
template <int N>
__device__ __forceinline__ void cp_wait() {
    asm volatile("cp.async.wait_group %0;" :: "n"(N) : "memory");
}

__device__ __forceinline__ void ldm_x4(uint32_t* r, uint32_t a) {
    asm volatile("ldmatrix.sync.aligned.m8n8.x4.shared.b16 {%0,%1,%2,%3}, [%4];"
                 : "=r"(r[0]), "=r"(r[1]), "=r"(r[2]), "=r"(r[3]) : "r"(a));
}
__device__ __forceinline__ void ldm_x4_trans(uint32_t* r, uint32_t a) {
    asm volatile("ldmatrix.sync.aligned.m8n8.x4.trans.shared.b16 {%0,%1,%2,%3}, [%4];"
                 : "=r"(r[0]), "=r"(r[1]), "=r"(r[2]), "=r"(r[3]) : "r"(a));
}
__device__ __forceinline__ void mma_f16(float* c, const uint32_t* a,
                                        uint32_t b0, uint32_t b1) {
    asm volatile(
        "mma.sync.aligned.m16n8k16.row.col.f32.f16.f16.f32 "
        "{%0,%1,%2,%3}, {%4,%5,%6,%7}, {%8,%9}, {%0,%1,%2,%3};"
        : "+f"(c[0]), "+f"(c[1]), "+f"(c[2]), "+f"(c[3])
        : "r"(a[0]), "r"(a[1]), "r"(a[2]), "r"(a[3]), "r"(b0), "r"(b1));
}

__device__ __forceinline__ float fsigmoid(float x) { return 1.0f / (1.0f + __expf(-x)); }
__device__ __forceinline__ float ftanh(float x)    { return 2.0f / (1.0f + __expf(-2.0f * x)) - 1.0f; }

__device__ __forceinline__ __half lo_plane(float v) {
    __half hi = __float2half_rn(v);
    return __float2half_rn((v - __half2float(hi)) * 2048.0f);
}

// ---------------- pack encoder W' ----------------
__global__ void pack_enc_kernel(const float* __restrict__ W_ih,
                                const float* __restrict__ W_hh,
                                const float* __restrict__ b) {
    int idx = blockIdx.x * blockDim.x + threadIdx.x;
    if (idx < NG * 640) {
        int n = idx / 640, kk = idx % 640;
        int j = n >> 2, g = n & 3;
        int row = g * HID + j;
        float v; bool lo;
        if (kk < 256)       { v = W_hh[row * HID + kk];          lo = true;  }
        else if (kk < 320)  { v = W_ih[row * EMB + (kk - 256)];  lo = true;  }
        else if (kk < 576)  { v = W_hh[row * HID + (kk - 320)];  lo = false; }
        else                { v = W_ih[row * EMB + (kk - 576)];  lo = false; }
        g_W_enc[idx] = lo ? lo_plane(v) : __float2half_rn(v);
    }
    if (idx < NG) {
        int j = idx >> 2, g = idx & 3;
        g_bias_enc[idx] = b[g * HID + j];
    }
}

// ---------------- pack decoder W' ----------------
__global__ void pack_dec_kernel(const float* __restrict__ W_ih,
                                const float* __restrict__ W_hh,
                                const float* __restrict__ b) {
    int idx = blockIdx.x * blockDim.x + threadIdx.x;
    if (idx < NG * 512) {
        int n = idx / 512, kk = idx % 512;
        int j = n >> 2, g = n & 3;
        int row = g * HID + j;
        if (kk < 256) g_W_dec[idx] = lo_plane(W_hh[row * HID + kk]);
        else          g_W_dec[idx] = __float2half_rn(W_hh[row * HID + (kk - 256)]);
    }
    if (idx < NG) {
        int j = idx >> 2, g = idx & 3;
        g_bias_dec[idx] = b[g * HID + j];
    }
    if (idx < NG * 2) {
        int n = idx >> 1, k = idx & 1;
        int j = n >> 2, g = n & 3;
        g_Wxd[idx] = W_ih[(g * HID + j) * INP + k];
    }
}

__global__ void init_state_kernel() {
    int idx = blockIdx.x * blockDim.x + threadIdx.x;
    if (idx < HID * BATCH) {
        g_H[0][idx] = __float2half(0.0f);
        g_c[idx]    = 0.0f;
    }
}

__global__ void init_out_kernel(const float* __restrict__ b_out,
                                float* __restrict__ out) {
    int idx = blockIdx.x * blockDim.x + threadIdx.x;
    if (idx < TLEN * BATCH * 2) out[idx] = b_out[idx & 1];
}

// ---------------- embedding -> [e][b] fp16 ----------------
__global__ void embed_kernel(const float* __restrict__ x,
                             const float* __restrict__ W_emb,
                             const float* __restrict__ b_emb) {
    int idx = blockIdx.x * blockDim.x + threadIdx.x;
    if (idx >= SEQ * EMB * BATCH) return;
    int b  = idx & (BATCH - 1);
    int te = idx >> 14;
    int e  = te & (EMB - 1);
    int t  = te >> 6;
    float x0 = x[((size_t)t * BATCH + b) * 2 + 0];
    float x1 = x[((size_t)t * BATCH + b) * 2 + 1];
    float v = b_emb[e] + x0 * W_emb[e * 2 + 0] + x1 * W_emb[e * 2 + 1];
    g_Xe[idx] = __float2half_rn(v);
}

// ---------------- fused HMMA LSTM step ----------------
// CTA 128(M batch)x128(N gates), 256 thr, 8 warps (2m x 4n), warp 64x32.
template <int MODE>
__global__ void __launch_bounds__(256, 2)
lstm_step_kernel(int t, int ppi,
                 const float* __restrict__ prev,   // MODE 2: [b][2] fp32
                 float* __restrict__ outp,         // MODE 2: out[t] [b][2]
                 const float* __restrict__ Wout) { // MODE 2: [2][256]
    constexpr int NCH    = (MODE == 0) ? 10 : (MODE == 1 ? 2 : 8);
    constexpr int LO_END = (MODE == 0) ? 4  : (MODE == 1 ? 0 : 3);
    constexpr int WS     = (MODE == 2) ? 512 : 640;
    extern __shared__ __align__(1024) char smem_raw[];
    const uint32_t sb = smem_to_u32(smem_raw);
    const int tid  = threadIdx.x;
    const int warp = tid >> 5, lane = tid & 31;
    const int wm = warp >> 2, wn = warp & 3;
    const int m0 = blockIdx.x * M_CTA, n0 = blockIdx.y * N_CTA;

    const __half* __restrict__ Wt  = (MODE == 2) ? g_W_dec : g_W_enc;
    const float* __restrict__ bias = (MODE == 2) ? g_bias_dec : g_bias_enc;
    const __half* __restrict__ hh  = g_H[ppi];
    __half* __restrict__ hho       = g_H[ppi ^ 1];
    const __half* __restrict__ xh  = g_Xe + (size_t)t * EMB * BATCH;

    // ---- chunk loader ----
    auto load_chunk = [&](int ck, int st) {
        const uint32_t sA = sb + st * STAGE_BYTES;
        const uint32_t sW = sA + A_TILE;
        const __half* ab;
        int woff;
        if (MODE == 0) {
            const int off = (ck < 5) ? ck : ck - 5;
            woff = (ck < 5) ? ck * KC : 320 + (ck - 5) * KC;
            ab = (off == 4) ? xh : hh + (size_t)(off * KC) * BATCH;
        } else if (MODE == 1) {
            ab = xh;
            woff = (ck == 0) ? 256 : 576;
        } else {
            woff = ck * KC;
            ab = hh + (size_t)((ck & 3) * KC) * BATCH;
        }
        // A: 64 rows x 256B; thread t: row t>>2, 4x16B cols
        {
            const int kr = tid >> 2;
            const __half* g = ab + (size_t)kr * BATCH + m0;
#pragma unroll
            for (int i = 0; i < 4; i++) {
                const int c16 = (tid & 3) * 4 + i;
                CP_ASYNC16(sA + SWZA(kr, c16), g + c16 * 8);
            }
        }
        // W: 128 rows x 128B; thread t: row t>>1, 4x16B segs
        {
            const int rw = tid >> 1;
            const __half* gw = Wt + (size_t)(n0 + rw) * WS + woff;
#pragma unroll
            for (int i = 0; i < 4; i++) {
                const int seg = (tid & 1) * 4 + i;
                CP_ASYNC16(sW + SWZ(rw * 128 + seg * 16), gw + seg * 8);
            }
        }
    };

    float acc[4][4][4];
#pragma unroll
    for (int a = 0; a < 4; a++)
#pragma unroll
        for (int b = 0; b < 4; b++)
#pragma unroll
            for (int c = 0; c < 4; c++) acc[a][b][c] = 0.0f;

    load_chunk(0, 0); CP_COMMIT();
    load_chunk(1, 1); CP_COMMIT();

    for (int ck = 0; ck < NCH; ck++) {
        const int st = ck % NSTAGE;
        cp_wait<1>();
        __syncthreads();
        if (ck + 2 < NCH) load_chunk(ck + 2, (ck + 2) % NSTAGE);
        CP_COMMIT();

        const uint32_t sA = sb + st * STAGE_BYTES;
        const uint32_t sW = sA + A_TILE;
#pragma unroll
        for (int k16 = 0; k16 < 4; k16++) {
            uint32_t afr[4][4];
            const int kr = k16 * 16 + (lane & 7) + ((lane & 16) >> 1);
#pragma unroll
            for (int mt = 0; mt < 4; mt++) {
                const int mc = wm * 64 + mt * 16 + (lane & 8);
                ldm_x4_trans(afr[mt], sA + SWZA(kr, mc >> 3));
            }
            uint32_t bfr[2][4];
#pragma unroll
            for (int p = 0; p < 2; p++) {
                const int row  = wn * 32 + p * 16 + (lane & 7) + ((lane & 16) >> 1);
                const int kcol = k16 * 16 + ((lane & 8) ? 8 : 0);
                ldm_x4(bfr[p], sW + SWZ(row * 128 + kcol * 2));
            }
#pragma unroll
            for (int mt = 0; mt < 4; mt++)
#pragma unroll
                for (int nt = 0; nt < 4; nt++)
                    mma_f16(acc[mt][nt], afr[mt],
                            bfr[nt >> 1][(nt & 1) * 2],
                            bfr[nt >> 1][(nt & 1) * 2 + 1]);
        }
        // lo-plane group done: fold its (x2048) contribution down once
        if (ck == LO_END) {
#pragma unroll
            for (int a = 0; a < 4; a++)
#pragma unroll
                for (int b = 0; b < 4; b++)
#pragma unroll
                    for (int c = 0; c < 4; c++) acc[a][b][c] *= INV2048;
        }
    }

    // ---- epilogue ----
    const int odd = lane & 1;
    const int q   = (lane & 2) >> 1;
    float s0m[4] = {0, 0, 0, 0}, s1m[4] = {0, 0, 0, 0};
    float xv0[4], xv1[4];
    if (MODE == 2) {
#pragma unroll
        for (int mt = 0; mt < 4; mt++) {
            const int mrow = m0 + wm * 64 + mt * 16 + (lane >> 2) + 8 * odd;
            xv0[mt] = prev[mrow * 2 + 0];
            xv1[mt] = prev[mrow * 2 + 1];
        }
    }
#pragma unroll
    for (int nt = 0; nt < 4; nt++) {
        const int nb = n0 + wn * 32 + nt * 8 + q * 4;
        const float4 bv = *(const float4*)&bias[nb];
        const int j = nb >> 2;
        float wx0[4], wx1[4], w_o0 = 0.0f, w_o1 = 0.0f;
        if (MODE == 2) {
#pragma unroll
            for (int r = 0; r < 4; r++) {
                wx0[r] = g_Wxd[(nb + r) * 2 + 0];
                wx1[r] = g_Wxd[(nb + r) * 2 + 1];
            }
            w_o0 = Wout[j];
            w_o1 = Wout[HID + j];
        }
#pragma unroll
        for (int mt = 0; mt < 4; mt++) {
            float o0 = __shfl_xor_sync(0xffffffffu, acc[mt][nt][0], 1);
            float o1 = __shfl_xor_sync(0xffffffffu, acc[mt][nt][1], 1);
            float o2 = __shfl_xor_sync(0xffffffffu, acc[mt][nt][2], 1);
            float o3 = __shfl_xor_sync(0xffffffffu, acc[mt][nt][3], 1);
            float gi, gf, gg, go;
            if (!odd) { gi = acc[mt][nt][0]; gf = acc[mt][nt][1]; gg = o0; go = o1; }
            else      { gi = o2; gf = o3; gg = acc[mt][nt][2]; go = acc[mt][nt][3]; }
            const int mrow = m0 + wm * 64 + mt * 16 + (lane >> 2) + 8 * odd;
            if (MODE == 2) {
                gi = fmaf(xv0[mt], wx0[0], fmaf(xv1[mt], wx1[0], gi));
                gf = fmaf(xv0[mt], wx0[1], fmaf(xv1[mt], wx1[1], gf));
                gg = fmaf(xv0[mt], wx0[2], fmaf(xv1[mt], wx1[2], gg));
                go = fmaf(xv0[mt], wx0[3], fmaf(xv1[mt], wx1[3], go));
            }
            gi += bv.x; gf += bv.y; gg += bv.z; go += bv.w;
            const size_t sidx = (size_t)j * BATCH + mrow;
            float cold = g_c[sidx];
            float cn = fsigmoid(gf) * cold + fsigmoid(gi) * ftanh(gg);
            g_c[sidx] = cn;
            float hn = fsigmoid(go) * ftanh(cn);
            hho[sidx] = __float2half_rn(hn);
            if (MODE == 2) {
                s0m[mt] = fmaf(hn, w_o0, s0m[mt]);
                s1m[mt] = fmaf(hn, w_o1, s1m[mt]);
            }
        }
    }

    // ---- MODE 2: reduce out partials and accumulate to out[t] ----
    if (MODE == 2) {
        float* sOut = (float*)smem_raw;   // 128 rows x 2
        __syncthreads();                  // all GEMM smem reads done
        sOut[tid] = 0.0f;
        __syncthreads();
#pragma unroll
        for (int mt = 0; mt < 4; mt++) {
            s0m[mt] += __shfl_xor_sync(0xffffffffu, s0m[mt], 2);
            s1m[mt] += __shfl_xor_sync(0xffffffffu, s1m[mt], 2);
        }
        if (!(lane & 2)) {
#pragma unroll
            for (int mt = 0; mt < 4; mt++) {
                const int r = wm * 64 + mt * 16 + (lane >> 2) + 8 * odd;
                atomicAdd(&sOut[r * 2 + 0], s0m[mt]);
                atomicAdd(&sOut[r * 2 + 1], s1m[mt]);
            }
        }
        __syncthreads();
        atomicAdd(&outp[(size_t)(m0 + (tid >> 1)) * 2 + (tid & 1)], sOut[tid]);
    }
}

// ---------------- launch ----------------
extern "C" void kernel_launch(void* const* d_in, const int* in_sizes, int n_in,
                              void* d_out, int out_size) {
    const float* x        = (const float*)d_in[0];
    const float* W_emb    = (const float*)d_in[1];
    const float* b_emb    = (const float*)d_in[2];
    const float* W_ih_enc = (const float*)d_in[3];
    const float* W_hh_enc = (const float*)d_in[4];
    const float* b_enc    = (const float*)d_in[5];
    const float* W_ih_dec = (const float*)d_in[6];
    const float* W_hh_dec = (const float*)d_in[7];
    const float* b_dec    = (const float*)d_in[8];
    const float* W_out    = (const float*)d_in[9];
    const float* b_out    = (const float*)d_in[10];
    float* out = (float*)d_out;

    cudaFuncSetAttribute(lstm_step_kernel<0>,
                         cudaFuncAttributeMaxDynamicSharedMemorySize, SMEM_DYN_TOTAL);
    cudaFuncSetAttribute(lstm_step_kernel<1>,
                         cudaFuncAttributeMaxDynamicSharedMemorySize, SMEM_DYN_TOTAL);
    cudaFuncSetAttribute(lstm_step_kernel<2>,
                         cudaFuncAttributeMaxDynamicSharedMemorySize, SMEM_DYN_TOTAL);

    pack_enc_kernel<<<(NG * 640 + 255) / 256, 256>>>(W_ih_enc, W_hh_enc, b_enc);
    pack_dec_kernel<<<(NG * 512 + 255) / 256, 256>>>(W_ih_dec, W_hh_dec, b_dec);
    init_state_kernel<<<(HID * BATCH + 255) / 256, 256>>>();
    init_out_kernel<<<(TLEN * BATCH * 2 + 255) / 256, 256>>>(b_out, out);
    embed_kernel<<<(SEQ * EMB * BATCH + 255) / 256, 256>>>(x, W_emb, b_emb);

    dim3 grid(BATCH / M_CTA, NG / N_CTA);   // (128, 8)
    int pp = 0;

    // encoder: t=0 has h=0 -> x-only GEMM
    lstm_step_kernel<1><<<grid, 256, SMEM_DYN_TOTAL>>>(0, pp, nullptr, nullptr, nullptr);
    pp ^= 1;
    for (int t = 1; t < SEQ; t++) {
        lstm_step_kernel<0><<<grid, 256, SMEM_DYN_TOTAL>>>(t, pp, nullptr, nullptr, nullptr);
        pp ^= 1;
    }
    // decoder: x injected in epilogue; out fused via atomics
    for (int t = 0; t < TLEN; t++) {
        const float* prev = (t == 0) ? (x + (size_t)(SEQ - 1) * BATCH * INP)
                                     : (out + (size_t)(t - 1) * BATCH * 2);
        lstm_step_kernel<2><<<grid, 256, SMEM_DYN_TOTAL>>>(
            0, pp, prev, out + (size_t)t * BATCH * 2, W_out);
        pp ^= 1;
    }
}

// round 8
// speedup vs baseline: 5.4440x; 1.3905x over previous
#include <cuda_runtime.h>
#include <cuda_fp16.h>
#include <cstdint>

#define SEQ   20
#define BATCH 16384
#define INP   2
#define HID   256
#define EMB   64
#define TLEN  30
#define NG    1024          /* 4*HID */
#define KC    64

#define M_CTA  128
#define N_CTA  128
#define NSTAGE 3
#define A_TILE 16384        /* 64 k-rows x 128 m-cols x 2B (row pitch 256B) */
#define B_TILE 16384        /* 128 n-rows x 64 k x 2B (row pitch 128B) */
#define STAGE_BYTES (A_TILE + B_TILE)         /* 32KB */
#define SMEM_DYN_TOTAL (NSTAGE * STAGE_BYTES) /* 96KB */

/* MODE: 0 = encoder (NCH 5: 4 h chunks + 1 x chunk),
         1 = encoder t=0, h=0 (NCH 1: x only),
         2 = decoder (NCH 4), x + out-projection fused in epilogue */

// ---------------- device scratch (all state [feature][batch]) ----------------
// enc W': [n][320] = Wh(h)[256] | Wx[64];  dec W': [n][256]
__device__ __half g_W_enc[NG * 320];
__device__ __half g_W_dec[NG * 256];
__device__ float g_Wxd[NG * 2];                 // decoder W_ih [n][2] fp32
__device__ float g_bias_enc[NG];
__device__ float g_bias_dec[NG];
__device__ __half g_H[2][HID * BATCH];          // [j][b] single fp16 plane
__device__ float g_c[HID * BATCH];              // [j][b]
__device__ __half g_Xe[SEQ * EMB * BATCH];      // [(t*64+e)][b]

// ---------------- helpers ----------------
__device__ __forceinline__ uint32_t smem_to_u32(const void* p) {
    uint32_t a;
    asm("{ .reg .u64 t; cvta.to.shared.u64 t, %1; cvt.u32.u64 %0, t; }"
        : "=r"(a) : "l"(p));
    return a;
}
#define SWZ(o) ((o) ^ (((o) >> 3) & 0x70))
#define SWZA(kr, c16) ((kr) * 256 + (((c16) ^ ((kr) & 7)) << 4))

#define CP_ASYNC16(s, g) \
    asm volatile("cp.async.cg.shared.global [%0], [%1], 16;" \
                 :: "r"((uint32_t)(s)), "l"(g) : "memory")
#define CP_COMMIT() asm volatile("cp.async.commit_group;" ::: "memory")
template <int N>
__device__ __forceinline__ void cp_wait() {
    asm volatile("cp.async.wait_group %0;" :: "n"(N) : "memory");
}

__device__ __forceinline__ void ldm_x4(uint32_t* r, uint32_t a) {
    asm volatile("ldmatrix.sync.aligned.m8n8.x4.shared.b16 {%0,%1,%2,%3}, [%4];"
                 : "=r"(r[0]), "=r"(r[1]), "=r"(r[2]), "=r"(r[3]) : "r"(a));
}
__device__ __forceinline__ void ldm_x4_trans(uint32_t* r, uint32_t a) {
    asm volatile("ldmatrix.sync.aligned.m8n8.x4.trans.shared.b16 {%0,%1,%2,%3}, [%4];"
                 : "=r"(r[0]), "=r"(r[1]), "=r"(r[2]), "=r"(r[3]) : "r"(a));
}
__device__ __forceinline__ void mma_f16(float* c, const uint32_t* a,
                                        uint32_t b0, uint32_t b1) {
    asm volatile(
        "mma.sync.aligned.m16n8k16.row.col.f32.f16.f16.f32 "
        "{%0,%1,%2,%3}, {%4,%5,%6,%7}, {%8,%9}, {%0,%1,%2,%3};"
        : "+f"(c[0]), "+f"(c[1]), "+f"(c[2]), "+f"(c[3])
        : "r"(a[0]), "r"(a[1]), "r"(a[2]), "r"(a[3]), "r"(b0), "r"(b1));
}

__device__ __forceinline__ float fsigmoid(float x) { return 1.0f / (1.0f + __expf(-x)); }
__device__ __forceinline__ float ftanh(float x)    { return 2.0f / (1.0f + __expf(-2.0f * x)) - 1.0f; }

// ---------------- pack encoder W' ----------------
__global__ void pack_enc_kernel(const float* __restrict__ W_ih,
                                const float* __restrict__ W_hh,
                                const float* __restrict__ b) {
    int idx = blockIdx.x * blockDim.x + threadIdx.x;
    if (idx < NG * 320) {
        int n = idx / 320, kk = idx % 320;
        int j = n >> 2, g = n & 3;
        int row = g * HID + j;
        float v = (kk < 256) ? W_hh[row * HID + kk] : W_ih[row * EMB + (kk - 256)];
        g_W_enc[idx] = __float2half_rn(v);
    }
    if (idx < NG) {
        int j = idx >> 2, g = idx & 3;
        g_bias_enc[idx] = b[g * HID + j];
    }
}

// ---------------- pack decoder W' ----------------
__global__ void pack_dec_kernel(const float* __restrict__ W_ih,
                                const float* __restrict__ W_hh,
                                const float* __restrict__ b) {
    int idx = blockIdx.x * blockDim.x + threadIdx.x;
    if (idx < NG * 256) {
        int n = idx / 256, kk = idx % 256;
        int j = n >> 2, g = n & 3;
        g_W_dec[idx] = __float2half_rn(W_hh[(g * HID + j) * HID + kk]);
    }
    if (idx < NG) {
        int j = idx >> 2, g = idx & 3;
        g_bias_dec[idx] = b[g * HID + j];
    }
    if (idx < NG * 2) {
        int n = idx >> 1, k = idx & 1;
        int j = n >> 2, g = n & 3;
        g_Wxd[idx] = W_ih[(g * HID + j) * INP + k];
    }
}

__global__ void init_state_kernel() {
    int idx = blockIdx.x * blockDim.x + threadIdx.x;
    if (idx < HID * BATCH) {
        g_H[0][idx] = __float2half(0.0f);
        g_c[idx]    = 0.0f;
    }
}

__global__ void init_out_kernel(const float* __restrict__ b_out,
                                float* __restrict__ out) {
    int idx = blockIdx.x * blockDim.x + threadIdx.x;
    if (idx < TLEN * BATCH * 2) out[idx] = b_out[idx & 1];
}

// ---------------- embedding -> [e][b] fp16 ----------------
__global__ void embed_kernel(const float* __restrict__ x,
                             const float* __restrict__ W_emb,
                             const float* __restrict__ b_emb) {
    int idx = blockIdx.x * blockDim.x + threadIdx.x;
    if (idx >= SEQ * EMB * BATCH) return;
    int b  = idx & (BATCH - 1);
    int te = idx >> 14;
    int e  = te & (EMB - 1);
    int t  = te >> 6;
    float x0 = x[((size_t)t * BATCH + b) * 2 + 0];
    float x1 = x[((size_t)t * BATCH + b) * 2 + 1];
    float v = b_emb[e] + x0 * W_emb[e * 2 + 0] + x1 * W_emb[e * 2 + 1];
    g_Xe[idx] = __float2half_rn(v);
}

// ---------------- fused HMMA LSTM step ----------------
// CTA 128(M batch)x128(N gates), 256 thr, 8 warps (2m x 4n), warp 64x32.
template <int MODE>
__global__ void __launch_bounds__(256, 2)
lstm_step_kernel(int t, int ppi,
                 const float* __restrict__ prev,   // MODE 2: [b][2] fp32
                 float* __restrict__ outp,         // MODE 2: out[t] [b][2]
                 const float* __restrict__ Wout) { // MODE 2: [2][256]
    constexpr int NCH = (MODE == 0) ? 5 : (MODE == 1 ? 1 : 4);
    constexpr int WS  = (MODE == 2) ? 256 : 320;
    extern __shared__ __align__(1024) char smem_raw[];
    const uint32_t sb = smem_to_u32(smem_raw);
    const int tid  = threadIdx.x;
    const int warp = tid >> 5, lane = tid & 31;
    const int wm = warp >> 2, wn = warp & 3;
    const int m0 = blockIdx.x * M_CTA, n0 = blockIdx.y * N_CTA;

    const __half* __restrict__ Wt  = (MODE == 2) ? g_W_dec : g_W_enc;
    const float* __restrict__ bias = (MODE == 2) ? g_bias_dec : g_bias_enc;
    const __half* __restrict__ hh  = g_H[ppi];
    __half* __restrict__ hho       = g_H[ppi ^ 1];
    const __half* __restrict__ xh  = g_Xe + (size_t)t * EMB * BATCH;

    // ---- chunk loader ----
    auto load_chunk = [&](int ck, int st) {
        const uint32_t sA = sb + st * STAGE_BYTES;
        const uint32_t sW = sA + A_TILE;
        const __half* ab;
        int woff;
        if (MODE == 0) {
            woff = ck * KC;
            ab = (ck == 4) ? xh : hh + (size_t)(ck * KC) * BATCH;
        } else if (MODE == 1) {
            ab = xh;
            woff = 256;
        } else {
            woff = ck * KC;
            ab = hh + (size_t)(ck * KC) * BATCH;
        }
        // A: 64 rows x 256B; thread t: row t>>2, 4x16B cols
        {
            const int kr = tid >> 2;
            const __half* g = ab + (size_t)kr * BATCH + m0;
#pragma unroll
            for (int i = 0; i < 4; i++) {
                const int c16 = (tid & 3) * 4 + i;
                CP_ASYNC16(sA + SWZA(kr, c16), g + c16 * 8);
            }
        }
        // W: 128 rows x 128B; thread t: row t>>1, 4x16B segs
        {
            const int rw = tid >> 1;
            const __half* gw = Wt + (size_t)(n0 + rw) * WS + woff;
#pragma unroll
            for (int i = 0; i < 4; i++) {
                const int seg = (tid & 1) * 4 + i;
                CP_ASYNC16(sW + SWZ(rw * 128 + seg * 16), gw + seg * 8);
            }
        }
    };

    float acc[4][4][4];
#pragma unroll
    for (int a = 0; a < 4; a++)
#pragma unroll
        for (int b = 0; b < 4; b++)
#pragma unroll
            for (int c = 0; c < 4; c++) acc[a][b][c] = 0.0f;

    load_chunk(0, 0); CP_COMMIT();
    if (NCH > 1) load_chunk(1, 1);
    CP_COMMIT();          // uniform 2 groups even when NCH == 1

    for (int ck = 0; ck < NCH; ck++) {
        const int st = ck % NSTAGE;
        cp_wait<1>();
        __syncthreads();
        if (ck + 2 < NCH) load_chunk(ck + 2, (ck + 2) % NSTAGE);
        CP_COMMIT();

        const uint32_t sA = sb + st * STAGE_BYTES;
        const uint32_t sW = sA + A_TILE;
#pragma unroll
        for (int k16 = 0; k16 < 4; k16++) {
            uint32_t afr[4][4];
            const int kr = k16 * 16 + (lane & 7) + ((lane & 16) >> 1);
#pragma unroll
            for (int mt = 0; mt < 4; mt++) {
                const int mc = wm * 64 + mt * 16 + (lane & 8);
                ldm_x4_trans(afr[mt], sA + SWZA(kr, mc >> 3));
            }
            uint32_t bfr[2][4];
#pragma unroll
            for (int p = 0; p < 2; p++) {
                const int row  = wn * 32 + p * 16 + (lane & 7) + ((lane & 16) >> 1);
                const int kcol = k16 * 16 + ((lane & 8) ? 8 : 0);
                ldm_x4(bfr[p], sW + SWZ(row * 128 + kcol * 2));
            }
#pragma unroll
            for (int mt = 0; mt < 4; mt++)
#pragma unroll
                for (int nt = 0; nt < 4; nt++)
                    mma_f16(acc[mt][nt], afr[mt],
                            bfr[nt >> 1][(nt & 1) * 2],
                            bfr[nt >> 1][(nt & 1) * 2 + 1]);
        }
    }

    // ---- epilogue ----
    const int odd = lane & 1;
    const int q   = (lane & 2) >> 1;
    float s0m[4] = {0, 0, 0, 0}, s1m[4] = {0, 0, 0, 0};
    float xv0[4], xv1[4];
    if (MODE == 2) {
#pragma unroll
        for (int mt = 0; mt < 4; mt++) {
            const int mrow = m0 + wm * 64 + mt * 16 + (lane >> 2) + 8 * odd;
            xv0[mt] = prev[mrow * 2 + 0];
            xv1[mt] = prev[mrow * 2 + 1];
        }
    }
#pragma unroll
    for (int nt = 0; nt < 4; nt++) {
        const int nb = n0 + wn * 32 + nt * 8 + q * 4;
        const float4 bv = *(const float4*)&bias[nb];
        const int j = nb >> 2;
        float wx0[4], wx1[4], w_o0 = 0.0f, w_o1 = 0.0f;
        if (MODE == 2) {
#pragma unroll
            for (int r = 0; r < 4; r++) {
                wx0[r] = g_Wxd[(nb + r) * 2 + 0];
                wx1[r] = g_Wxd[(nb + r) * 2 + 1];
            }
            w_o0 = Wout[j];
            w_o1 = Wout[HID + j];
        }
#pragma unroll
        for (int mt = 0; mt < 4; mt++) {
            float o0 = __shfl_xor_sync(0xffffffffu, acc[mt][nt][0], 1);
            float o1 = __shfl_xor_sync(0xffffffffu, acc[mt][nt][1], 1);
            float o2 = __shfl_xor_sync(0xffffffffu, acc[mt][nt][2], 1);
            float o3 = __shfl_xor_sync(0xffffffffu, acc[mt][nt][3], 1);
            float gi, gf, gg, go;
            if (!odd) { gi = acc[mt][nt][0]; gf = acc[mt][nt][1]; gg = o0; go = o1; }
            else      { gi = o2; gf = o3; gg = acc[mt][nt][2]; go = acc[mt][nt][3]; }
            const int mrow = m0 + wm * 64 + mt * 16 + (lane >> 2) + 8 * odd;
            if (MODE == 2) {
                gi = fmaf(xv0[mt], wx0[0], fmaf(xv1[mt], wx1[0], gi));
                gf = fmaf(xv0[mt], wx0[1], fmaf(xv1[mt], wx1[1], gf));
                gg = fmaf(xv0[mt], wx0[2], fmaf(xv1[mt], wx1[2], gg));
                go = fmaf(xv0[mt], wx0[3], fmaf(xv1[mt], wx1[3], go));
            }
            gi += bv.x; gf += bv.y; gg += bv.z; go += bv.w;
            const size_t sidx = (size_t)j * BATCH + mrow;
            float cold = (MODE == 1) ? 0.0f : g_c[sidx];
            float cn = fsigmoid(gf) * cold + fsigmoid(gi) * ftanh(gg);
            g_c[sidx] = cn;
            float hn = fsigmoid(go) * ftanh(cn);
            hho[sidx] = __float2half_rn(hn);
            if (MODE == 2) {
                s0m[mt] = fmaf(hn, w_o0, s0m[mt]);
                s1m[mt] = fmaf(hn, w_o1, s1m[mt]);
            }
        }
    }

    // ---- MODE 2: reduce out partials and accumulate to out[t] ----
    if (MODE == 2) {
        float* sOut = (float*)smem_raw;   // 128 rows x 2
        __syncthreads();                  // all GEMM smem reads done
        sOut[tid] = 0.0f;
        __syncthreads();
#pragma unroll
        for (int mt = 0; mt < 4; mt++) {
            s0m[mt] += __shfl_xor_sync(0xffffffffu, s0m[mt], 2);
            s1m[mt] += __shfl_xor_sync(0xffffffffu, s1m[mt], 2);
        }
        if (!(lane & 2)) {
#pragma unroll
            for (int mt = 0; mt < 4; mt++) {
                const int r = wm * 64 + mt * 16 + (lane >> 2) + 8 * odd;
                atomicAdd(&sOut[r * 2 + 0], s0m[mt]);
                atomicAdd(&sOut[r * 2 + 1], s1m[mt]);
            }
        }
        __syncthreads();
        atomicAdd(&outp[(size_t)(m0 + (tid >> 1)) * 2 + (tid & 1)], sOut[tid]);
    }
}

// ---------------- launch ----------------
extern "C" void kernel_launch(void* const* d_in, const int* in_sizes, int n_in,
                              void* d_out, int out_size) {
    const float* x        = (const float*)d_in[0];
    const float* W_emb    = (const float*)d_in[1];
    const float* b_emb    = (const float*)d_in[2];
    const float* W_ih_enc = (const float*)d_in[3];
    const float* W_hh_enc = (const float*)d_in[4];
    const float* b_enc    = (const float*)d_in[5];
    const float* W_ih_dec = (const float*)d_in[6];
    const float* W_hh_dec = (const float*)d_in[7];
    const float* b_dec    = (const float*)d_in[8];
    const float* W_out    = (const float*)d_in[9];
    const float* b_out    = (const float*)d_in[10];
    float* out = (float*)d_out;

    cudaFuncSetAttribute(lstm_step_kernel<0>,
                         cudaFuncAttributeMaxDynamicSharedMemorySize, SMEM_DYN_TOTAL);
    cudaFuncSetAttribute(lstm_step_kernel<1>,
                         cudaFuncAttributeMaxDynamicSharedMemorySize, SMEM_DYN_TOTAL);
    cudaFuncSetAttribute(lstm_step_kernel<2>,
                         cudaFuncAttributeMaxDynamicSharedMemorySize, SMEM_DYN_TOTAL);

    pack_enc_kernel<<<(NG * 320 + 255) / 256, 256>>>(W_ih_enc, W_hh_enc, b_enc);
    pack_dec_kernel<<<(NG * 256 + 255) / 256, 256>>>(W_ih_dec, W_hh_dec, b_dec);
    init_state_kernel<<<(HID * BATCH + 255) / 256, 256>>>();
    init_out_kernel<<<(TLEN * BATCH * 2 + 255) / 256, 256>>>(b_out, out);
    embed_kernel<<<(SEQ * EMB * BATCH + 255) / 256, 256>>>(x, W_emb, b_emb);

    dim3 grid(BATCH / M_CTA, NG / N_CTA);   // (128, 8)
    int pp = 0;

    // encoder: t=0 has h=0 -> x-only GEMM
    lstm_step_kernel<1><<<grid, 256, SMEM_DYN_TOTAL>>>(0, pp, nullptr, nullptr, nullptr);
    pp ^= 1;
    for (int t = 1; t < SEQ; t++) {
        lstm_step_kernel<0><<<grid, 256, SMEM_DYN_TOTAL>>>(t, pp, nullptr, nullptr, nullptr);
        pp ^= 1;
    }
    // decoder: x injected in epilogue; out fused via atomics
    for (int t = 0; t < TLEN; t++) {
        const float* prev = (t == 0) ? (x + (size_t)(SEQ - 1) * BATCH * INP)
                                     : (out + (size_t)(t - 1) * BATCH * 2);
        lstm_step_kernel<2><<<grid, 256, SMEM_DYN_TOTAL>>>(
            0, pp, prev, out + (size_t)t * BATCH * 2, W_out);
        pp ^= 1;
    }
}

// round 9
// speedup vs baseline: 5.9198x; 1.0874x over previous
#include <cuda_runtime.h>
#include <cuda_fp16.h>
#include <cstdint>

#define SEQ   20
#define BATCH 16384
#define INP   2
#define HID   256
#define EMB   64
#define TLEN  30
#define NG    1024          /* 4*HID */
#define KC    64

#define M_CTA  128
#define N_CTA  128
#define NSTAGE 3
#define A_TILE 16384        /* 64 k-rows x 128 m-cols x 2B (row pitch 256B) */
#define B_TILE 16384        /* 128 n-rows x 64 k x 2B (row pitch 128B) */
#define STAGE_BYTES (A_TILE + B_TILE)         /* 32KB */
#define SMEM_DYN_TOTAL (NSTAGE * STAGE_BYTES) /* 96KB */

/* MODE: 0 = encoder (NCH 5: chunk0 = x, chunks 1..4 = h),
         1 = encoder t=0, h=0 (NCH 1: x only),
         2 = decoder (NCH 4 h chunks), x + out-projection fused in epilogue */

// ---------------- device scratch (all state [feature][batch]) ----------------
// enc W': [n][320] = Wh(h)[256] | Wx[64];  dec W': [n][256]
__device__ __half g_W_enc[NG * 320];
__device__ __half g_W_dec[NG * 256];
__device__ float g_Wxd[NG * 2];                 // decoder W_ih [n][2] fp32
__device__ float g_bias_enc[NG];
__device__ float g_bias_dec[NG];
__device__ __half g_H[2][HID * BATCH];          // [j][b] single fp16 plane
__device__ float g_c[HID * BATCH];              // [j][b]
__device__ __half g_Xe[SEQ * EMB * BATCH];      // [(t*64+e)][b]

// ---------------- helpers ----------------
__device__ __forceinline__ uint32_t smem_to_u32(const void* p) {
    uint32_t a;
    asm("{ .reg .u64 t; cvta.to.shared.u64 t, %1; cvt.u32.u64 %0, t; }"
        : "=r"(a) : "l"(p));
    return a;
}
#define SWZ(o) ((o) ^ (((o) >> 3) & 0x70))
#define SWZA(kr, c16) ((kr) * 256 + (((c16) ^ ((kr) & 7)) << 4))

#define CP_ASYNC16(s, g) \
    asm volatile("cp.async.cg.shared.global [%0], [%1], 16;" \
                 :: "r"((uint32_t)(s)), "l"(g) : "memory")
#define CP_COMMIT() asm volatile("cp.async.commit_group;" ::: "memory")
template <int N>
__device__ __forceinline__ void cp_wait() {
    asm volatile("cp.async.wait_group %0;" :: "n"(N) : "memory");
}

#define PDL_WAIT()    asm volatile("griddepcontrol.wait;" ::: "memory")
#define PDL_TRIGGER() asm volatile("griddepcontrol.launch_dependents;" ::: "memory")

__device__ __forceinline__ void ldm_x4(uint32_t* r, uint32_t a) {
    asm volatile("ldmatrix.sync.aligned.m8n8.x4.shared.b16 {%0,%1,%2,%3}, [%4];"
                 : "=r"(r[0]), "=r"(r[1]), "=r"(r[2]), "=r"(r[3]) : "r"(a));
}
__device__ __forceinline__ void ldm_x4_trans(uint32_t* r, uint32_t a) {
    asm volatile("ldmatrix.sync.aligned.m8n8.x4.trans.shared.b16 {%0,%1,%2,%3}, [%4];"
                 : "=r"(r[0]), "=r"(r[1]), "=r"(r[2]), "=r"(r[3]) : "r"(a));
}
__device__ __forceinline__ void mma_f16(float* c, const uint32_t* a,
                                        uint32_t b0, uint32_t b1) {
    asm volatile(
        "mma.sync.aligned.m16n8k16.row.col.f32.f16.f16.f32 "
        "{%0,%1,%2,%3}, {%4,%5,%6,%7}, {%8,%9}, {%0,%1,%2,%3};"
        : "+f"(c[0]), "+f"(c[1]), "+f"(c[2]), "+f"(c[3])
        : "r"(a[0]), "r"(a[1]), "r"(a[2]), "r"(a[3]), "r"(b0), "r"(b1));
}

__device__ __forceinline__ float fsigmoid(float x) { return 1.0f / (1.0f + __expf(-x)); }
__device__ __forceinline__ float ftanh(float x)    { return 2.0f / (1.0f + __expf(-2.0f * x)) - 1.0f; }

// ---------------- pack encoder W' ----------------
__global__ void pack_enc_kernel(const float* __restrict__ W_ih,
                                const float* __restrict__ W_hh,
                                const float* __restrict__ b) {
    int idx = blockIdx.x * blockDim.x + threadIdx.x;
    if (idx < NG * 320) {
        int n = idx / 320, kk = idx % 320;
        int j = n >> 2, g = n & 3;
        int row = g * HID + j;
        float v = (kk < 256) ? W_hh[row * HID + kk] : W_ih[row * EMB + (kk - 256)];
        g_W_enc[idx] = __float2half_rn(v);
    }
    if (idx < NG) {
        int j = idx >> 2, g = idx & 3;
        g_bias_enc[idx] = b[g * HID + j];
    }
}

// ---------------- pack decoder W' ----------------
__global__ void pack_dec_kernel(const float* __restrict__ W_ih,
                                const float* __restrict__ W_hh,
                                const float* __restrict__ b) {
    int idx = blockIdx.x * blockDim.x + threadIdx.x;
    if (idx < NG * 256) {
        int n = idx / 256, kk = idx % 256;
        int j = n >> 2, g = n & 3;
        g_W_dec[idx] = __float2half_rn(W_hh[(g * HID + j) * HID + kk]);
    }
    if (idx < NG) {
        int j = idx >> 2, g = idx & 3;
        g_bias_dec[idx] = b[g * HID + j];
    }
    if (idx < NG * 2) {
        int n = idx >> 1, k = idx & 1;
        int j = n >> 2, g = n & 3;
        g_Wxd[idx] = W_ih[(g * HID + j) * INP + k];
    }
}

__global__ void init_state_kernel() {
    int idx = blockIdx.x * blockDim.x + threadIdx.x;
    if (idx < HID * BATCH) {
        g_H[0][idx] = __float2half(0.0f);
        g_c[idx]    = 0.0f;
    }
}

__global__ void init_out_kernel(const float* __restrict__ b_out,
                                float* __restrict__ out) {
    int idx = blockIdx.x * blockDim.x + threadIdx.x;
    if (idx < TLEN * BATCH * 2) out[idx] = b_out[idx & 1];
}

// ---------------- embedding -> [e][b] fp16 ----------------
__global__ void embed_kernel(const float* __restrict__ x,
                             const float* __restrict__ W_emb,
                             const float* __restrict__ b_emb) {
    int idx = blockIdx.x * blockDim.x + threadIdx.x;
    if (idx >= SEQ * EMB * BATCH) return;
    int b  = idx & (BATCH - 1);
    int te = idx >> 14;
    int e  = te & (EMB - 1);
    int t  = te >> 6;
    float x0 = x[((size_t)t * BATCH + b) * 2 + 0];
    float x1 = x[((size_t)t * BATCH + b) * 2 + 1];
    float v = b_emb[e] + x0 * W_emb[e * 2 + 0] + x1 * W_emb[e * 2 + 1];
    g_Xe[idx] = __float2half_rn(v);
}

// ---------------- fused HMMA LSTM step ----------------
// CTA 128(M batch)x128(N gates), 256 thr, 8 warps (2m x 4n), warp 64x32.
template <int MODE>
__global__ void __launch_bounds__(256, 2)
lstm_step_kernel(int t, int ppi,
                 const float* __restrict__ prev,   // MODE 2: [b][2] fp32
                 float* __restrict__ outp,         // MODE 2: out[t] [b][2]
                 const float* __restrict__ Wout) { // MODE 2: [2][256]
    constexpr int NCH = (MODE == 0) ? 5 : (MODE == 1 ? 1 : 4);
    constexpr int WS  = (MODE == 2) ? 256 : 320;
    extern __shared__ __align__(1024) char smem_raw[];
    const uint32_t sb = smem_to_u32(smem_raw);
    const int tid  = threadIdx.x;
    const int warp = tid >> 5, lane = tid & 31;
    const int wm = warp >> 2, wn = warp & 3;
    const int m0 = blockIdx.x * M_CTA, n0 = blockIdx.y * N_CTA;

    const __half* __restrict__ Wt  = (MODE == 2) ? g_W_dec : g_W_enc;
    const float* __restrict__ bias = (MODE == 2) ? g_bias_dec : g_bias_enc;
    const __half* __restrict__ hh  = g_H[ppi];
    __half* __restrict__ hho       = g_H[ppi ^ 1];
    const __half* __restrict__ xh  = g_Xe + (size_t)t * EMB * BATCH;

    // chunk -> (A source, W offset). MODE0: ck0 = x (PDL-independent).
    auto a_src = [&](int ck) -> const __half* {
        if (MODE == 0) return (ck == 0) ? xh : hh + (size_t)((ck - 1) * KC) * BATCH;
        if (MODE == 1) return xh;
        return hh + (size_t)(ck * KC) * BATCH;
    };
    auto w_off = [&](int ck) -> int {
        if (MODE == 0) return (ck == 0) ? 256 : (ck - 1) * KC;
        if (MODE == 1) return 256;
        return ck * KC;
    };

    auto load_W = [&](int ck, int st) {
        const uint32_t sW = sb + st * STAGE_BYTES + A_TILE;
        const int rw = tid >> 1;
        const __half* gw = Wt + (size_t)(n0 + rw) * WS + w_off(ck);
#pragma unroll
        for (int i = 0; i < 4; i++) {
            const int seg = (tid & 1) * 4 + i;
            CP_ASYNC16(sW + SWZ(rw * 128 + seg * 16), gw + seg * 8);
        }
    };
    auto load_A = [&](int ck, int st) {
        const uint32_t sA = sb + st * STAGE_BYTES;
        const int kr = tid >> 2;
        const __half* g = a_src(ck) + (size_t)kr * BATCH + m0;
#pragma unroll
        for (int i = 0; i < 4; i++) {
            const int c16 = (tid & 3) * 4 + i;
            CP_ASYNC16(sA + SWZA(kr, c16), g + c16 * 8);
        }
    };

    float acc[4][4][4];
#pragma unroll
    for (int a = 0; a < 4; a++)
#pragma unroll
        for (int b = 0; b < 4; b++)
#pragma unroll
            for (int c = 0; c < 4; c++) acc[a][b][c] = 0.0f;

    // ---- prologue: PDL-independent loads first, wait, then h-dependent A ----
    if (MODE == 0) {
        load_W(0, 0); load_A(0, 0); CP_COMMIT();   // x chunk: fully independent
        load_W(1, 1);
        PDL_WAIT();
        load_A(1, 1); CP_COMMIT();
    } else if (MODE == 1) {
        load_W(0, 0); load_A(0, 0); CP_COMMIT();
        CP_COMMIT();    // uniform 2 groups
    } else {
        load_W(0, 0); load_W(1, 1);
        PDL_WAIT();
        load_A(0, 0); CP_COMMIT();
        load_A(1, 1); CP_COMMIT();
    }

    for (int ck = 0; ck < NCH; ck++) {
        const int st = ck % NSTAGE;
        cp_wait<1>();
        __syncthreads();
        if (ck + 2 < NCH) {
            const int st2 = (ck + 2) % NSTAGE;
            load_W(ck + 2, st2);
            load_A(ck + 2, st2);
        }
        CP_COMMIT();

        const uint32_t sA = sb + st * STAGE_BYTES;
        const uint32_t sW = sA + A_TILE;
#pragma unroll
        for (int k16 = 0; k16 < 4; k16++) {
            uint32_t afr[4][4];
            const int kr = k16 * 16 + (lane & 7) + ((lane & 16) >> 1);
#pragma unroll
            for (int mt = 0; mt < 4; mt++) {
                const int mc = wm * 64 + mt * 16 + (lane & 8);
                ldm_x4_trans(afr[mt], sA + SWZA(kr, mc >> 3));
            }
            uint32_t bfr[2][4];
#pragma unroll
            for (int p = 0; p < 2; p++) {
                const int row  = wn * 32 + p * 16 + (lane & 7) + ((lane & 16) >> 1);
                const int kcol = k16 * 16 + ((lane & 8) ? 8 : 0);
                ldm_x4(bfr[p], sW + SWZ(row * 128 + kcol * 2));
            }
#pragma unroll
            for (int mt = 0; mt < 4; mt++)
#pragma unroll
                for (int nt = 0; nt < 4; nt++)
                    mma_f16(acc[mt][nt], afr[mt],
                            bfr[nt >> 1][(nt & 1) * 2],
                            bfr[nt >> 1][(nt & 1) * 2 + 1]);
        }
    }

    // mainloop done: release the next step's launch (overlaps our epilogue)
    PDL_TRIGGER();

    // ---- epilogue ----
    const int odd = lane & 1;
    const int q   = (lane & 2) >> 1;
    float s0m[4] = {0, 0, 0, 0}, s1m[4] = {0, 0, 0, 0};
    float xv0[4], xv1[4];
    if (MODE == 2) {
#pragma unroll
        for (int mt = 0; mt < 4; mt++) {
            const int mrow = m0 + wm * 64 + mt * 16 + (lane >> 2) + 8 * odd;
            xv0[mt] = prev[mrow * 2 + 0];
            xv1[mt] = prev[mrow * 2 + 1];
        }
    }
#pragma unroll
    for (int nt = 0; nt < 4; nt++) {
        const int nb = n0 + wn * 32 + nt * 8 + q * 4;
        const float4 bv = *(const float4*)&bias[nb];
        const int j = nb >> 2;
        float wx0[4], wx1[4], w_o0 = 0.0f, w_o1 = 0.0f;
        if (MODE == 2) {
#pragma unroll
            for (int r = 0; r < 4; r++) {
                wx0[r] = g_Wxd[(nb + r) * 2 + 0];
                wx1[r] = g_Wxd[(nb + r) * 2 + 1];
            }
            w_o0 = Wout[j];
            w_o1 = Wout[HID + j];
        }
#pragma unroll
        for (int mt = 0; mt < 4; mt++) {
            float o0 = __shfl_xor_sync(0xffffffffu, acc[mt][nt][0], 1);
            float o1 = __shfl_xor_sync(0xffffffffu, acc[mt][nt][1], 1);
            float o2 = __shfl_xor_sync(0xffffffffu, acc[mt][nt][2], 1);
            float o3 = __shfl_xor_sync(0xffffffffu, acc[mt][nt][3], 1);
            float gi, gf, gg, go;
            if (!odd) { gi = acc[mt][nt][0]; gf = acc[mt][nt][1]; gg = o0; go = o1; }
            else      { gi = o2; gf = o3; gg = acc[mt][nt][2]; go = acc[mt][nt][3]; }
            const int mrow = m0 + wm * 64 + mt * 16 + (lane >> 2) + 8 * odd;
            if (MODE == 2) {
                gi = fmaf(xv0[mt], wx0[0], fmaf(xv1[mt], wx1[0], gi));
                gf = fmaf(xv0[mt], wx0[1], fmaf(xv1[mt], wx1[1], gf));
                gg = fmaf(xv0[mt], wx0[2], fmaf(xv1[mt], wx1[2], gg));
                go = fmaf(xv0[mt], wx0[3], fmaf(xv1[mt], wx1[3], go));
            }
            gi += bv.x; gf += bv.y; gg += bv.z; go += bv.w;
            const size_t sidx = (size_t)j * BATCH + mrow;
            float cold = (MODE == 1) ? 0.0f : g_c[sidx];
            float cn = fsigmoid(gf) * cold + fsigmoid(gi) * ftanh(gg);
            g_c[sidx] = cn;
            float hn = fsigmoid(go) * ftanh(cn);
            hho[sidx] = __float2half_rn(hn);
            if (MODE == 2) {
                s0m[mt] = fmaf(hn, w_o0, s0m[mt]);
                s1m[mt] = fmaf(hn, w_o1, s1m[mt]);
            }
        }
    }

    // ---- MODE 2: reduce out partials and accumulate to out[t] ----
    if (MODE == 2) {
        float* sOut = (float*)smem_raw;   // 128 rows x 2
        __syncthreads();                  // all GEMM smem reads done
        sOut[tid] = 0.0f;
        __syncthreads();
#pragma unroll
        for (int mt = 0; mt < 4; mt++) {
            s0m[mt] += __shfl_xor_sync(0xffffffffu, s0m[mt], 2);
            s1m[mt] += __shfl_xor_sync(0xffffffffu, s1m[mt], 2);
        }
        if (!(lane & 2)) {
#pragma unroll
            for (int mt = 0; mt < 4; mt++) {
                const int r = wm * 64 + mt * 16 + (lane >> 2) + 8 * odd;
                atomicAdd(&sOut[r * 2 + 0], s0m[mt]);
                atomicAdd(&sOut[r * 2 + 1], s1m[mt]);
            }
        }
        __syncthreads();
        atomicAdd(&outp[(size_t)(m0 + (tid >> 1)) * 2 + (tid & 1)], sOut[tid]);
    }
}

// ---------------- host-side PDL launch helper ----------------
template <int MODE>
static void launch_step(dim3 grid, bool pdl, int t, int pp,
                        const float* prev, float* outp, const float* Wout) {
    cudaLaunchConfig_t cfg = {};
    cfg.gridDim = grid;
    cfg.blockDim = dim3(256, 1, 1);
    cfg.dynamicSmemBytes = SMEM_DYN_TOTAL;
    cfg.stream = 0;
    cudaLaunchAttribute attr[1];
    if (pdl) {
        attr[0].id = cudaLaunchAttributeProgrammaticStreamSerialization;
        attr[0].val.programmaticStreamSerializationAllowed = 1;
        cfg.attrs = attr;
        cfg.numAttrs = 1;
    }
    cudaLaunchKernelEx(&cfg, lstm_step_kernel<MODE>, t, pp, prev, outp, Wout);
}

// ---------------- launch ----------------
extern "C" void kernel_launch(void* const* d_in, const int* in_sizes, int n_in,
                              void* d_out, int out_size) {
    const float* x        = (const float*)d_in[0];
    const float* W_emb    = (const float*)d_in[1];
    const float* b_emb    = (const float*)d_in[2];
    const float* W_ih_enc = (const float*)d_in[3];
    const float* W_hh_enc = (const float*)d_in[4];
    const float* b_enc    = (const float*)d_in[5];
    const float* W_ih_dec = (const float*)d_in[6];
    const float* W_hh_dec = (const float*)d_in[7];
    const float* b_dec    = (const float*)d_in[8];
    const float* W_out    = (const float*)d_in[9];
    const float* b_out    = (const float*)d_in[10];
    float* out = (float*)d_out;

    cudaFuncSetAttribute(lstm_step_kernel<0>,
                         cudaFuncAttributeMaxDynamicSharedMemorySize, SMEM_DYN_TOTAL);
    cudaFuncSetAttribute(lstm_step_kernel<1>,
                         cudaFuncAttributeMaxDynamicSharedMemorySize, SMEM_DYN_TOTAL);
    cudaFuncSetAttribute(lstm_step_kernel<2>,
                         cudaFuncAttributeMaxDynamicSharedMemorySize, SMEM_DYN_TOTAL);

    pack_enc_kernel<<<(NG * 320 + 255) / 256, 256>>>(W_ih_enc, W_hh_enc, b_enc);
    pack_dec_kernel<<<(NG * 256 + 255) / 256, 256>>>(W_ih_dec, W_hh_dec, b_dec);
    init_state_kernel<<<(HID * BATCH + 255) / 256, 256>>>();
    init_out_kernel<<<(TLEN * BATCH * 2 + 255) / 256, 256>>>(b_out, out);
    embed_kernel<<<(SEQ * EMB * BATCH + 255) / 256, 256>>>(x, W_emb, b_emb);

    dim3 grid(BATCH / M_CTA, NG / N_CTA);   // (128, 8)
    int pp = 0;

    // encoder: t=0 has h=0 -> x-only GEMM (no PDL: depends on embed/init)
    launch_step<1>(grid, false, 0, pp, nullptr, nullptr, nullptr);
    pp ^= 1;
    for (int t = 1; t < SEQ; t++) {
        launch_step<0>(grid, true, t, pp, nullptr, nullptr, nullptr);
        pp ^= 1;
    }
    // decoder: x injected in epilogue; out fused via atomics
    for (int t = 0; t < TLEN; t++) {
        const float* prev = (t == 0) ? (x + (size_t)(SEQ - 1) * BATCH * INP)
                                     : (out + (size_t)(t - 1) * BATCH * 2);
        launch_step<2>(grid, true, 0, pp, prev, out + (size_t)t * BATCH * 2, W_out);
        pp ^= 1;
    }
}